// round 2
// baseline (speedup 1.0000x reference)
#include <cuda_runtime.h>
#include <cstdint>
#include <cstddef>

// ---------------- problem dims ----------------
#define kB   8
#define kSP  1024
#define kSF  1024
#define kS   2048
#define kXD  6
#define kD   512
#define kL   4
#define kH   8
#define kW   128
#define kDH  64
#define kC   16
#define kFF  2048
#define kM   (kB * kS)          // 16384 rows

// ---------------- scratch (__device__ globals; no runtime alloc) ----------------
__device__ float g_h   [(size_t)kB * kS * kD];
__device__ float g_ln  [(size_t)kB * kS * kD];
__device__ float g_q   [(size_t)kB * kS * kD];
__device__ float g_k   [(size_t)kB * kS * kD];
__device__ float g_v   [(size_t)kB * kS * kD];
__device__ float g_attn[(size_t)kB * kS * kD];
__device__ float g_ffn [(size_t)kB * kS * kFF];
__device__ float g_scores[(size_t)kB * kH * kC * kS];
__device__ float g_cnt [(size_t)kB * kH * kS];
__device__ int   g_iq  [(size_t)kB * kH * kC * kW];
__device__ int   g_ik  [(size_t)kB * kH * kC * kW];

// ---------------- helpers ----------------
__device__ __forceinline__ float gelu_tanh(float x) {
    float x3 = x * x * x;
    return 0.5f * x * (1.0f + tanhf(0.7978845608028654f * (x + 0.044715f * x3)));
}

// ---------------- embedding ----------------
__global__ void embed_kernel(const float* __restrict__ past_x,
                             const float* __restrict__ past_y,
                             const float* __restrict__ future_x,
                             const float* __restrict__ W_emb,
                             const float* __restrict__ b_emb,
                             float* __restrict__ h) {
    int idx = blockIdx.x * blockDim.x + threadIdx.x;
    if (idx >= kB * kS * kD) return;
    int d = idx % kD;
    int s = (idx / kD) % kS;
    int b = idx / (kD * kS);
    float feat[kXD + 1];
    if (s < kSP) {
#pragma unroll
        for (int j = 0; j < kXD; j++) feat[j] = past_x[((size_t)b * kSP + s) * kXD + j];
        feat[kXD] = past_y[(size_t)b * kSP + s];
    } else {
        int sf = s - kSP;
#pragma unroll
        for (int j = 0; j < kXD; j++) feat[j] = future_x[((size_t)b * kSF + sf) * kXD + j];
        feat[kXD] = past_y[(size_t)b * kSP + (kSP - 1)];
    }
    float acc = b_emb[d];
#pragma unroll
    for (int j = 0; j < kXD + 1; j++) acc += feat[j] * W_emb[(size_t)j * kD + d];
    h[idx] = acc;
}

// ---------------- layernorm (block per row, 128 threads) ----------------
__global__ void ln_kernel(const float* __restrict__ x, float* __restrict__ y,
                          const float* __restrict__ g, const float* __restrict__ bb) {
    __shared__ float red[8];
    int row = blockIdx.x;
    int t = threadIdx.x;
    const float4 xv = ((const float4*)(x + (size_t)row * kD))[t];
    float s = xv.x + xv.y + xv.z + xv.w;
#pragma unroll
    for (int o = 16; o; o >>= 1) s += __shfl_xor_sync(0xffffffffu, s, o);
    if ((t & 31) == 0) red[t >> 5] = s;
    __syncthreads();
    float mean = (red[0] + red[1] + red[2] + red[3]) * (1.0f / kD);
    float dx = xv.x - mean, dy = xv.y - mean, dz = xv.z - mean, dw = xv.w - mean;
    float s2 = dx * dx + dy * dy + dz * dz + dw * dw;
#pragma unroll
    for (int o = 16; o; o >>= 1) s2 += __shfl_xor_sync(0xffffffffu, s2, o);
    if ((t & 31) == 0) red[4 + (t >> 5)] = s2;
    __syncthreads();
    float var = (red[4] + red[5] + red[6] + red[7]) * (1.0f / kD);
    float rstd = rsqrtf(var + 1e-5f);
    const float4 gg = ((const float4*)g)[t];
    const float4 bv = ((const float4*)bb)[t];
    float4 o4;
    o4.x = dx * rstd * gg.x + bv.x;
    o4.y = dy * rstd * gg.y + bv.y;
    o4.z = dz * rstd * gg.z + bv.z;
    o4.w = dw * rstd * gg.w + bv.w;
    ((float4*)(y + (size_t)row * kD))[t] = o4;
}

// ---------------- SGEMM: C = act(A@B + bias + res) ----------------
// 128x128 tile, TBK=16, double-buffered SMEM, register-staged global loads.
#define TBM 128
#define TBN 128
#define TBK 16
__global__ __launch_bounds__(256) void sgemm_kernel(
    const float* __restrict__ A, const float* __restrict__ Bm,
    const float* __restrict__ bias, const float* __restrict__ res,
    float* __restrict__ Cm, int M, int N, int K, int act) {
    __shared__ float As[2][TBK][TBM];
    __shared__ float Bs[2][TBK][TBN];
    int tid = threadIdx.x;
    int bx = blockIdx.x, by = blockIdx.y;
    int tx = tid % 16, ty = tid / 16;
    const float* Ab = A + (size_t)by * TBM * K;
    const float* Bb = Bm + (size_t)bx * TBN;

    float acc[8][8];
#pragma unroll
    for (int i = 0; i < 8; i++)
#pragma unroll
        for (int j = 0; j < 8; j++) acc[i][j] = 0.f;

    // load mapping
    int aRow = tid >> 1;            // 0..127
    int aCol = (tid & 1) * 8;       // 0 or 8
    int bRow = tid >> 5;            // 0..7 (and +8)
    int bCol = (tid & 31) * 4;

    const float* Aptr = Ab + (size_t)aRow * K + aCol;

    float4 a0, a1, b0, b1;
    // prologue: load tile 0 into buffer 0
    a0 = *(const float4*)(Aptr + 0);
    a1 = *(const float4*)(Aptr + 4);
    b0 = *(const float4*)(Bb + (size_t)bRow * N + bCol);
    b1 = *(const float4*)(Bb + (size_t)(bRow + 8) * N + bCol);
    As[0][aCol + 0][aRow] = a0.x; As[0][aCol + 1][aRow] = a0.y;
    As[0][aCol + 2][aRow] = a0.z; As[0][aCol + 3][aRow] = a0.w;
    As[0][aCol + 4][aRow] = a1.x; As[0][aCol + 5][aRow] = a1.y;
    As[0][aCol + 6][aRow] = a1.z; As[0][aCol + 7][aRow] = a1.w;
    *(float4*)(&Bs[0][bRow][bCol]) = b0;
    *(float4*)(&Bs[0][bRow + 8][bCol]) = b1;
    __syncthreads();

    int nk = K / TBK;
    for (int kb = 0; kb < nk; kb++) {
        int cur = kb & 1, nxt = cur ^ 1;
        // issue next tile's global loads first (latency hidden under compute)
        if (kb + 1 < nk) {
            int k0 = (kb + 1) * TBK;
            a0 = *(const float4*)(Aptr + k0);
            a1 = *(const float4*)(Aptr + k0 + 4);
            b0 = *(const float4*)(Bb + (size_t)(k0 + bRow) * N + bCol);
            b1 = *(const float4*)(Bb + (size_t)(k0 + bRow + 8) * N + bCol);
        }
#pragma unroll
        for (int kk = 0; kk < TBK; kk++) {
            float ar[8], br[8];
            *(float4*)(ar + 0) = *(const float4*)(&As[cur][kk][ty * 8 + 0]);
            *(float4*)(ar + 4) = *(const float4*)(&As[cur][kk][ty * 8 + 4]);
            *(float4*)(br + 0) = *(const float4*)(&Bs[cur][kk][tx * 8 + 0]);
            *(float4*)(br + 4) = *(const float4*)(&Bs[cur][kk][tx * 8 + 4]);
#pragma unroll
            for (int i = 0; i < 8; i++)
#pragma unroll
                for (int j = 0; j < 8; j++) acc[i][j] += ar[i] * br[j];
        }
        if (kb + 1 < nk) {
            As[nxt][aCol + 0][aRow] = a0.x; As[nxt][aCol + 1][aRow] = a0.y;
            As[nxt][aCol + 2][aRow] = a0.z; As[nxt][aCol + 3][aRow] = a0.w;
            As[nxt][aCol + 4][aRow] = a1.x; As[nxt][aCol + 5][aRow] = a1.y;
            As[nxt][aCol + 6][aRow] = a1.z; As[nxt][aCol + 7][aRow] = a1.w;
            *(float4*)(&Bs[nxt][bRow][bCol]) = b0;
            *(float4*)(&Bs[nxt][bRow + 8][bCol]) = b1;
        }
        __syncthreads();
    }

    // epilogue (vectorized)
    int col0 = bx * TBN + tx * 8;
    float4 bias0, bias1;
    if (bias) {
        bias0 = *(const float4*)(bias + col0);
        bias1 = *(const float4*)(bias + col0 + 4);
    }
#pragma unroll
    for (int i = 0; i < 8; i++) {
        int row = by * TBM + ty * 8 + i;
        float* crow = Cm + (size_t)row * N + col0;
        float v[8];
#pragma unroll
        for (int j = 0; j < 8; j++) v[j] = acc[i][j];
        if (bias) {
            v[0] += bias0.x; v[1] += bias0.y; v[2] += bias0.z; v[3] += bias0.w;
            v[4] += bias1.x; v[5] += bias1.y; v[6] += bias1.z; v[7] += bias1.w;
        }
        if (res) {
            const float* rrow = res + (size_t)row * N + col0;
            float4 r0 = *(const float4*)(rrow);
            float4 r1 = *(const float4*)(rrow + 4);
            v[0] += r0.x; v[1] += r0.y; v[2] += r0.z; v[3] += r0.w;
            v[4] += r1.x; v[5] += r1.y; v[6] += r1.z; v[7] += r1.w;
        }
        if (act) {
#pragma unroll
            for (int j = 0; j < 8; j++) v[j] = gelu_tanh(v[j]);
        }
        float4 o0 = make_float4(v[0], v[1], v[2], v[3]);
        float4 o1 = make_float4(v[4], v[5], v[6], v[7]);
        *(float4*)(crow) = o0;
        *(float4*)(crow + 4) = o1;
    }
}

// ---------------- routing scores ----------------
__global__ void score_kernel(const float* __restrict__ qk,
                             const float* __restrict__ means,
                             float* __restrict__ scores) {
    int bs = blockIdx.x;
    int b = bs / kS, s = bs % kS;
    int h = threadIdx.x >> 5, lane = threadIdx.x & 31;
    const float* qrow = qk + (size_t)bs * kD + h * kDH;
    float qa = qrow[lane], qb = qrow[lane + 32];
    float nrm = qa * qa + qb * qb;
#pragma unroll
    for (int o = 16; o; o >>= 1) nrm += __shfl_xor_sync(0xffffffffu, nrm, o);
    float rn = rsqrtf(nrm + 1e-8f);
#pragma unroll
    for (int c = 0; c < kC; c++) {
        const float* mrow = means + ((size_t)h * kC + c) * kDH;
        float p = qa * mrow[lane] + qb * mrow[lane + 32];
#pragma unroll
        for (int o = 16; o; o >>= 1) p += __shfl_xor_sync(0xffffffffu, p, o);
        if (lane == 0)
            scores[(((size_t)b * kH + h) * kC + c) * kS + s] = p * rn;
    }
}

// ---------------- top-W via bitonic sort ----------------
__global__ void topk_kernel(const float* __restrict__ scores, int* __restrict__ idxout) {
    __shared__ unsigned long long keys[kS];
    int blk = blockIdx.x;
    const float* sp = scores + (size_t)blk * kS;
    for (int i = threadIdx.x; i < kS; i += blockDim.x) {
        unsigned u = __float_as_uint(sp[i]);
        u = (u & 0x80000000u) ? ~u : (u | 0x80000000u);
        keys[i] = ((unsigned long long)u << 32) | (unsigned)i;
    }
    __syncthreads();
    for (int k = 2; k <= kS; k <<= 1) {
        for (int j = k >> 1; j > 0; j >>= 1) {
            for (int i = threadIdx.x; i < kS; i += blockDim.x) {
                int ixj = i ^ j;
                if (ixj > i) {
                    unsigned long long a = keys[i], b = keys[ixj];
                    bool up = ((i & k) == 0);
                    bool sw = up ? (a < b) : (a > b);
                    if (sw) { keys[i] = b; keys[ixj] = a; }
                }
            }
            __syncthreads();
        }
    }
    if (threadIdx.x < kW)
        idxout[(size_t)blk * kW + threadIdx.x] = (int)(keys[threadIdx.x] & 0xffffffffu);
}

// ---------------- within-cluster attention + scatter-add ----------------
__global__ __launch_bounds__(128) void attn_kernel(
    const float* __restrict__ q, const float* __restrict__ k, const float* __restrict__ v,
    const int* __restrict__ iq, const int* __restrict__ ik,
    float* __restrict__ attnout, float* __restrict__ cnt) {
    int blk = blockIdx.x;
    int h = (blk / kC) % kH;
    int b = blk / (kC * kH);
    extern __shared__ float smem[];
    float* ks = smem;
    float* vs = smem + kW * kDH;
    int t = threadIdx.x;
    const int* ikp = ik + (size_t)blk * kW;
    const int* iqp = iq + (size_t)blk * kW;
    {
        int sk = ikp[t];
        const float4* krow = (const float4*)(k + ((size_t)b * kS + sk) * kD + h * kDH);
        const float4* vrow = (const float4*)(v + ((size_t)b * kS + sk) * kD + h * kDH);
        float4* ksr = (float4*)(ks + (size_t)t * kDH);
        float4* vsr = (float4*)(vs + (size_t)t * kDH);
#pragma unroll
        for (int i = 0; i < kDH / 4; i++) { ksr[i] = krow[i]; vsr[i] = vrow[i]; }
    }
    __syncthreads();
    int sq = iqp[t];
    float qreg[kDH];
    {
        const float4* qrow = (const float4*)(q + ((size_t)b * kS + sq) * kD + h * kDH);
#pragma unroll
        for (int i = 0; i < kDH / 4; i++) ((float4*)qreg)[i] = qrow[i];
    }
    float m = -1e30f, l = 0.f;
    float accv[kDH];
#pragma unroll
    for (int d = 0; d < kDH; d++) accv[d] = 0.f;
    const float scale = 0.125f;

    for (int j = 0; j < kW; j++) {
        const float* kj = ks + (size_t)j * kDH;
        float s0 = 0, s1 = 0, s2 = 0, s3 = 0;
#pragma unroll
        for (int d = 0; d < kDH; d += 4) {
            s0 += qreg[d + 0] * kj[d + 0];
            s1 += qreg[d + 1] * kj[d + 1];
            s2 += qreg[d + 2] * kj[d + 2];
            s3 += qreg[d + 3] * kj[d + 3];
        }
        float s = (s0 + s1 + s2 + s3) * scale;
        float mn = fmaxf(m, s);
        float corr = __expf(m - mn);
        float p = __expf(s - mn);
        l = l * corr + p;
        const float* vj = vs + (size_t)j * kDH;
#pragma unroll
        for (int d = 0; d < kDH; d++) accv[d] = accv[d] * corr + p * vj[d];
        m = mn;
    }
    float inv = 1.0f / l;
    float* orow = attnout + ((size_t)b * kS + sq) * kD + h * kDH;
#pragma unroll
    for (int d = 0; d < kDH; d++) atomicAdd(orow + d, accv[d] * inv);
    atomicAdd(cnt + ((size_t)b * kH + h) * kS + sq, 1.0f);
}

// ---------------- scatter-mean divide ----------------
__global__ void divcnt_kernel(float* __restrict__ attn, const float* __restrict__ cnt) {
    int idx = blockIdx.x * blockDim.x + threadIdx.x;
    if (idx >= kB * kS * kD) return;
    int d = idx % kD;
    int h = d >> 6;
    int s = (idx / kD) % kS;
    int b = idx / (kD * kS);
    float c = cnt[((size_t)b * kH + h) * kS + s];
    attn[idx] = attn[idx] / fmaxf(c, 1.0f);
}

// ---------------- output heads ----------------
__global__ void head_kernel(const float* __restrict__ hln,
                            const float* __restrict__ Wm, const float* __restrict__ bm,
                            const float* __restrict__ Ws, const float* __restrict__ bsd,
                            float* __restrict__ out) {
    int warp = (blockIdx.x * blockDim.x + threadIdx.x) >> 5;
    int lane = threadIdx.x & 31;
    if (warp >= kB * kSF) return;
    int b = warp / kSF, sf = warp % kSF;
    const float* row = hln + ((size_t)b * kS + kSP + sf) * kD;
    float mdot = 0.f, sdot = 0.f;
    for (int d = lane; d < kD; d += 32) {
        float x = row[d];
        mdot += x * Wm[d];
        sdot += x * Ws[d];
    }
#pragma unroll
    for (int o = 16; o; o >>= 1) {
        mdot += __shfl_xor_sync(0xffffffffu, mdot, o);
        sdot += __shfl_xor_sync(0xffffffffu, sdot, o);
    }
    if (lane == 0) {
        out[warp] = mdot + bm[0];
        float ls = sdot + bsd[0];
        float sp = fmaxf(ls, 0.f) + log1pf(__expf(-fabsf(ls)));
        out[(size_t)kB * kSF + warp] = 0.01f + 0.99f * sp;
    }
}

// ---------------- host orchestration ----------------
static void launch_gemm(const float* A, const float* Bm, const float* bias,
                        const float* res, float* C, int M, int N, int K, int act) {
    dim3 grid(N / TBN, M / TBM);
    sgemm_kernel<<<grid, 256>>>(A, Bm, bias, res, C, M, N, K, act);
}

extern "C" void kernel_launch(void* const* d_in, const int* in_sizes, int n_in,
                              void* d_out, int out_size) {
    const float* past_x   = (const float*)d_in[0];
    const float* past_y   = (const float*)d_in[1];
    const float* future_x = (const float*)d_in[2];
    const float* W_emb    = (const float*)d_in[3];
    const float* b_emb    = (const float*)d_in[4];
    const float* ln1_g    = (const float*)d_in[5];
    const float* ln1_b    = (const float*)d_in[6];
    const float* Wq       = (const float*)d_in[7];
    const float* Wk       = (const float*)d_in[8];
    const float* Wv       = (const float*)d_in[9];
    const float* Wo       = (const float*)d_in[10];
    const float* means    = (const float*)d_in[11];
    const float* ln2_g    = (const float*)d_in[12];
    const float* ln2_b    = (const float*)d_in[13];
    const float* W1       = (const float*)d_in[14];
    const float* b1       = (const float*)d_in[15];
    const float* W2       = (const float*)d_in[16];
    const float* b2       = (const float*)d_in[17];
    const float* lnf_g    = (const float*)d_in[18];
    const float* lnf_b    = (const float*)d_in[19];
    const float* W_mean   = (const float*)d_in[20];
    const float* b_mean   = (const float*)d_in[21];
    const float* W_std    = (const float*)d_in[22];
    const float* b_std    = (const float*)d_in[23];

    void *ph, *pln, *pq, *pk, *pv, *pattn, *pffn, *pscores, *pcnt, *piq, *pik;
    cudaGetSymbolAddress(&ph, g_h);
    cudaGetSymbolAddress(&pln, g_ln);
    cudaGetSymbolAddress(&pq, g_q);
    cudaGetSymbolAddress(&pk, g_k);
    cudaGetSymbolAddress(&pv, g_v);
    cudaGetSymbolAddress(&pattn, g_attn);
    cudaGetSymbolAddress(&pffn, g_ffn);
    cudaGetSymbolAddress(&pscores, g_scores);
    cudaGetSymbolAddress(&pcnt, g_cnt);
    cudaGetSymbolAddress(&piq, g_iq);
    cudaGetSymbolAddress(&pik, g_ik);
    float* h    = (float*)ph;
    float* ln   = (float*)pln;
    float* q    = (float*)pq;
    float* k    = (float*)pk;
    float* v    = (float*)pv;
    float* attn = (float*)pattn;
    float* ffn  = (float*)pffn;
    float* scr  = (float*)pscores;
    float* cnt  = (float*)pcnt;
    int*   iq   = (int*)piq;
    int*   ik   = (int*)pik;

    const int attn_smem = 2 * kW * kDH * (int)sizeof(float);  // 64 KB
    cudaFuncSetAttribute(attn_kernel, cudaFuncAttributeMaxDynamicSharedMemorySize, attn_smem);

    {
        int total = kB * kS * kD;
        embed_kernel<<<(total + 255) / 256, 256>>>(past_x, past_y, future_x, W_emb, b_emb, h);
    }

    for (int l = 0; l < kL; l++) {
        const float* mns = means + (size_t)l * kH * kC * kDH;
        // --- attention block ---
        ln_kernel<<<kM, 128>>>(h, ln, ln1_g + (size_t)l * kD, ln1_b + (size_t)l * kD);
        launch_gemm(ln, Wq + (size_t)l * kD * kD, nullptr, nullptr, q, kM, kD, kD, 0);
        launch_gemm(ln, Wk + (size_t)l * kD * kD, nullptr, nullptr, k, kM, kD, kD, 0);
        launch_gemm(ln, Wv + (size_t)l * kD * kD, nullptr, nullptr, v, kM, kD, kD, 0);

        score_kernel<<<kM, 256>>>(q, mns, scr);
        topk_kernel<<<kB * kH * kC, 1024>>>(scr, iq);
        score_kernel<<<kM, 256>>>(k, mns, scr);
        topk_kernel<<<kB * kH * kC, 1024>>>(scr, ik);

        cudaMemsetAsync(attn, 0, (size_t)kB * kS * kD * sizeof(float), 0);
        cudaMemsetAsync(cnt, 0, (size_t)kB * kH * kS * sizeof(float), 0);
        attn_kernel<<<kB * kH * kC, 128, attn_smem>>>(q, k, v, iq, ik, attn, cnt);
        {
            int total = kB * kS * kD;
            divcnt_kernel<<<(total + 255) / 256, 256>>>(attn, cnt);
        }
        launch_gemm(attn, Wo + (size_t)l * kD * kD, nullptr, h, h, kM, kD, kD, 0);

        // --- FFN block ---
        ln_kernel<<<kM, 128>>>(h, ln, ln2_g + (size_t)l * kD, ln2_b + (size_t)l * kD);
        launch_gemm(ln, W1 + (size_t)l * kD * kFF, b1 + (size_t)l * kFF, nullptr, ffn, kM, kFF, kD, 1);
        launch_gemm(ffn, W2 + (size_t)l * kFF * kD, b2 + (size_t)l * kD, h, h, kM, kD, kFF, 0);
    }

    ln_kernel<<<kM, 128>>>(h, ln, lnf_g, lnf_b);
    {
        int warps = kB * kSF;
        int threads = warps * 32;
        head_kernel<<<(threads + 255) / 256, 256>>>(ln, W_mean, b_mean, W_std, b_std, (float*)d_out);
    }
}

// round 8
// speedup vs baseline: 1.0931x; 1.0931x over previous
#include <cuda_runtime.h>
#include <cstdint>
#include <cstddef>

// ---------------- problem dims ----------------
#define kB   8
#define kSP  1024
#define kSF  1024
#define kS   2048
#define kXD  6
#define kD   512
#define kL   4
#define kH   8
#define kW   128
#define kDH  64
#define kC   16
#define kFF  2048
#define kM   (kB * kS)          // 16384 rows

// ---------------- scratch (__device__ globals; no runtime alloc) ----------------
__device__ float g_h   [(size_t)kB * kS * kD];
__device__ float g_ln  [(size_t)kB * kS * kD];
__device__ float g_q   [(size_t)kB * kS * kD];
__device__ float g_k   [(size_t)kB * kS * kD];
__device__ float g_v   [(size_t)kB * kS * kD];
__device__ float g_attn[(size_t)kB * kS * kD];
__device__ float g_ffn [(size_t)kB * kS * kFF];
__device__ float g_scores[(size_t)kB * kH * kC * kS];
__device__ float g_cnt [(size_t)kB * kH * kS];
__device__ int   g_iq  [(size_t)kB * kH * kC * kW];
__device__ int   g_ik  [(size_t)kB * kH * kC * kW];

// ---------------- helpers ----------------
__device__ __forceinline__ float gelu_tanh(float x) {
    float x3 = x * x * x;
    return 0.5f * x * (1.0f + tanhf(0.7978845608028654f * (x + 0.044715f * x3)));
}

__device__ __forceinline__ uint32_t smem_u32(const void* p) {
    uint32_t a;
    asm("{ .reg .u64 t; cvta.to.shared.u64 t, %1; cvt.u32.u64 %0, t; }" : "=r"(a) : "l"(p));
    return a;
}

__device__ __forceinline__ void cp_async16(uint32_t dst, const void* src) {
    asm volatile("cp.async.cg.shared.global [%0], [%1], 16;" :: "r"(dst), "l"(src) : "memory");
}
__device__ __forceinline__ void cp_commit() { asm volatile("cp.async.commit_group;" ::: "memory"); }
__device__ __forceinline__ void cp_wait0()  { asm volatile("cp.async.wait_group 0;" ::: "memory"); }

// ---------------- fp32 SGEMM, TBK=16, cp.async double-buffered ----------------
// Per-output FMA order identical to the R1 kernel: k ascending, serial.
// (TBK=16 merges two R1 k-blocks; the FMA sequence per accumulator is unchanged.)
#define TBM 128
#define TBN 128
#define TBK 16
__global__ __launch_bounds__(256, 2) void sgemm_kernel(
    const float* __restrict__ A, const float* __restrict__ Bm,
    const float* __restrict__ bias, const float* __restrict__ res,
    float* __restrict__ Cm, int M, int N, int K, int act) {
    __shared__ float As[2][TBK][TBM];
    __shared__ float Bs[2][TBK][TBN];
    int tid = threadIdx.x;
    int bx = blockIdx.x, by = blockIdx.y;
    int tx = tid % 16, ty = tid / 16;
    const float* Ab = A + (size_t)by * TBM * K;
    const float* Bb = Bm + (size_t)bx * TBN;
    float acc[8][8];
#pragma unroll
    for (int i = 0; i < 8; i++)
#pragma unroll
        for (int j = 0; j < 8; j++) acc[i][j] = 0.f;

    // load mapping
    int aRow = tid >> 1, aCol = (tid & 1) * 8;       // A: 128 rows x 16 cols, 2 float4/thread
    int bRow = tid >> 5, bCol = (tid & 31) * 4;      // B: rows bRow and bRow+8, 2 cp.async/thread

    uint32_t bs_base = smem_u32(&Bs[0][0][0]);
    const float* Aptr = Ab + (size_t)aRow * K + aCol;

    // prologue: fill buffer 0 with k-block 0
    {
        cp_async16(bs_base + ((size_t)(0 * TBK + bRow) * TBN + bCol) * 4,
                   Bb + (size_t)bRow * N + bCol);
        cp_async16(bs_base + ((size_t)(0 * TBK + bRow + 8) * TBN + bCol) * 4,
                   Bb + (size_t)(bRow + 8) * N + bCol);
        cp_commit();
        float4 a0 = *(const float4*)(Aptr);
        float4 a1 = *(const float4*)(Aptr + 4);
        As[0][aCol + 0][aRow] = a0.x; As[0][aCol + 1][aRow] = a0.y;
        As[0][aCol + 2][aRow] = a0.z; As[0][aCol + 3][aRow] = a0.w;
        As[0][aCol + 4][aRow] = a1.x; As[0][aCol + 5][aRow] = a1.y;
        As[0][aCol + 6][aRow] = a1.z; As[0][aCol + 7][aRow] = a1.w;
        cp_wait0();
    }
    __syncthreads();

    int nk = K / TBK;
    for (int kb = 0; kb < nk; kb++) {
        int cur = kb & 1, nxt = cur ^ 1;
        float4 a0, a1;
        bool pf = (kb + 1 < nk);
        if (pf) {
            int k0 = (kb + 1) * TBK;
            cp_async16(bs_base + ((size_t)(nxt * TBK + bRow) * TBN + bCol) * 4,
                       Bb + (size_t)(k0 + bRow) * N + bCol);
            cp_async16(bs_base + ((size_t)(nxt * TBK + bRow + 8) * TBN + bCol) * 4,
                       Bb + (size_t)(k0 + bRow + 8) * N + bCol);
            cp_commit();
            a0 = *(const float4*)(Aptr + k0);
            a1 = *(const float4*)(Aptr + k0 + 4);
        }
#pragma unroll
        for (int k = 0; k < TBK; k++) {
            float ar[8], br[8];
#pragma unroll
            for (int i = 0; i < 8; i += 4) *(float4*)(ar + i) = *(const float4*)(&As[cur][k][ty * 8 + i]);
#pragma unroll
            for (int j = 0; j < 8; j += 4) *(float4*)(br + j) = *(const float4*)(&Bs[cur][k][tx * 8 + j]);
#pragma unroll
            for (int i = 0; i < 8; i++)
#pragma unroll
                for (int j = 0; j < 8; j++) acc[i][j] += ar[i] * br[j];
        }
        if (pf) {
            As[nxt][aCol + 0][aRow] = a0.x; As[nxt][aCol + 1][aRow] = a0.y;
            As[nxt][aCol + 2][aRow] = a0.z; As[nxt][aCol + 3][aRow] = a0.w;
            As[nxt][aCol + 4][aRow] = a1.x; As[nxt][aCol + 5][aRow] = a1.y;
            As[nxt][aCol + 6][aRow] = a1.z; As[nxt][aCol + 7][aRow] = a1.w;
            cp_wait0();
        }
        __syncthreads();
    }

    // epilogue (identical numerics to R1)
#pragma unroll
    for (int i = 0; i < 8; i++) {
        int row = by * TBM + ty * 8 + i;
        int col0 = bx * TBN + tx * 8;
        float* crow = Cm + (size_t)row * N + col0;
        const float* rrow = res ? res + (size_t)row * N + col0 : nullptr;
#pragma unroll
        for (int j = 0; j < 8; j++) {
            float v = acc[i][j];
            if (bias) v += bias[col0 + j];
            if (rrow) v += rrow[j];
            if (act) v = gelu_tanh(v);
            crow[j] = v;
        }
    }
}

// ---------------- embedding ----------------
__global__ void embed_kernel(const float* __restrict__ past_x,
                             const float* __restrict__ past_y,
                             const float* __restrict__ future_x,
                             const float* __restrict__ W_emb,
                             const float* __restrict__ b_emb,
                             float* __restrict__ h) {
    int idx = blockIdx.x * blockDim.x + threadIdx.x;
    if (idx >= kB * kS * kD) return;
    int d = idx % kD;
    int s = (idx / kD) % kS;
    int b = idx / (kD * kS);
    float feat[kXD + 1];
    if (s < kSP) {
#pragma unroll
        for (int j = 0; j < kXD; j++) feat[j] = past_x[((size_t)b * kSP + s) * kXD + j];
        feat[kXD] = past_y[(size_t)b * kSP + s];
    } else {
        int sf = s - kSP;
#pragma unroll
        for (int j = 0; j < kXD; j++) feat[j] = future_x[((size_t)b * kSF + sf) * kXD + j];
        feat[kXD] = past_y[(size_t)b * kSP + (kSP - 1)];
    }
    float acc = b_emb[d];
#pragma unroll
    for (int j = 0; j < kXD + 1; j++) acc += feat[j] * W_emb[(size_t)j * kD + d];
    h[idx] = acc;
}

// ---------------- layernorm (block per row, 128 threads) ----------------
__global__ void ln_kernel(const float* __restrict__ x, float* __restrict__ y,
                          const float* __restrict__ g, const float* __restrict__ bb) {
    __shared__ float red[8];
    int row = blockIdx.x;
    int t = threadIdx.x;
    const float4 xv = ((const float4*)(x + (size_t)row * kD))[t];
    float s = xv.x + xv.y + xv.z + xv.w;
#pragma unroll
    for (int o = 16; o; o >>= 1) s += __shfl_xor_sync(0xffffffffu, s, o);
    if ((t & 31) == 0) red[t >> 5] = s;
    __syncthreads();
    float mean = (red[0] + red[1] + red[2] + red[3]) * (1.0f / kD);
    float dx = xv.x - mean, dy = xv.y - mean, dz = xv.z - mean, dw = xv.w - mean;
    float s2 = dx * dx + dy * dy + dz * dz + dw * dw;
#pragma unroll
    for (int o = 16; o; o >>= 1) s2 += __shfl_xor_sync(0xffffffffu, s2, o);
    if ((t & 31) == 0) red[4 + (t >> 5)] = s2;
    __syncthreads();
    float var = (red[4] + red[5] + red[6] + red[7]) * (1.0f / kD);
    float rstd = rsqrtf(var + 1e-5f);
    const float4 gg = ((const float4*)g)[t];
    const float4 bv = ((const float4*)bb)[t];
    float4 o4;
    o4.x = dx * rstd * gg.x + bv.x;
    o4.y = dy * rstd * gg.y + bv.y;
    o4.z = dz * rstd * gg.z + bv.z;
    o4.w = dw * rstd * gg.w + bv.w;
    ((float4*)(y + (size_t)row * kD))[t] = o4;
}

// ---------------- routing scores ----------------
__global__ void score_kernel(const float* __restrict__ qk,
                             const float* __restrict__ means,
                             float* __restrict__ scores) {
    int bs = blockIdx.x;
    int b = bs / kS, s = bs % kS;
    int h = threadIdx.x >> 5, lane = threadIdx.x & 31;
    const float* qrow = qk + (size_t)bs * kD + h * kDH;
    float qa = qrow[lane], qb = qrow[lane + 32];
    float nrm = qa * qa + qb * qb;
#pragma unroll
    for (int o = 16; o; o >>= 1) nrm += __shfl_xor_sync(0xffffffffu, nrm, o);
    float rn = rsqrtf(nrm + 1e-8f);
#pragma unroll
    for (int c = 0; c < kC; c++) {
        const float* mrow = means + ((size_t)h * kC + c) * kDH;
        float p = qa * mrow[lane] + qb * mrow[lane + 32];
#pragma unroll
        for (int o = 16; o; o >>= 1) p += __shfl_xor_sync(0xffffffffu, p, o);
        if (lane == 0)
            scores[(((size_t)b * kH + h) * kC + c) * kS + s] = p * rn;
    }
}

// ---------------- top-W via bitonic sort ----------------
__global__ void topk_kernel(const float* __restrict__ scores, int* __restrict__ idxout) {
    __shared__ unsigned long long keys[kS];
    int blk = blockIdx.x;
    const float* sp = scores + (size_t)blk * kS;
    for (int i = threadIdx.x; i < kS; i += blockDim.x) {
        unsigned u = __float_as_uint(sp[i]);
        u = (u & 0x80000000u) ? ~u : (u | 0x80000000u);
        keys[i] = ((unsigned long long)u << 32) | (unsigned)i;
    }
    __syncthreads();
    for (int k = 2; k <= kS; k <<= 1) {
        for (int j = k >> 1; j > 0; j >>= 1) {
            for (int i = threadIdx.x; i < kS; i += blockDim.x) {
                int ixj = i ^ j;
                if (ixj > i) {
                    unsigned long long a = keys[i], b = keys[ixj];
                    bool up = ((i & k) == 0);
                    bool sw = up ? (a < b) : (a > b);
                    if (sw) { keys[i] = b; keys[ixj] = a; }
                }
            }
            __syncthreads();
        }
    }
    if (threadIdx.x < kW)
        idxout[(size_t)blk * kW + threadIdx.x] = (int)(keys[threadIdx.x] & 0xffffffffu);
}

// ---------------- within-cluster attention + scatter-add ----------------
__global__ __launch_bounds__(128) void attn_kernel(
    const float* __restrict__ q, const float* __restrict__ k, const float* __restrict__ v,
    const int* __restrict__ iq, const int* __restrict__ ik,
    float* __restrict__ attnout, float* __restrict__ cnt) {
    int blk = blockIdx.x;
    int h = (blk / kC) % kH;
    int b = blk / (kC * kH);
    extern __shared__ float smem[];
    float* ks = smem;
    float* vs = smem + kW * kDH;
    int t = threadIdx.x;
    const int* ikp = ik + (size_t)blk * kW;
    const int* iqp = iq + (size_t)blk * kW;
    {
        int sk = ikp[t];
        const float4* krow = (const float4*)(k + ((size_t)b * kS + sk) * kD + h * kDH);
        const float4* vrow = (const float4*)(v + ((size_t)b * kS + sk) * kD + h * kDH);
        float4* ksr = (float4*)(ks + (size_t)t * kDH);
        float4* vsr = (float4*)(vs + (size_t)t * kDH);
#pragma unroll
        for (int i = 0; i < kDH / 4; i++) { ksr[i] = krow[i]; vsr[i] = vrow[i]; }
    }
    __syncthreads();
    int sq = iqp[t];
    float qreg[kDH];
    {
        const float4* qrow = (const float4*)(q + ((size_t)b * kS + sq) * kD + h * kDH);
#pragma unroll
        for (int i = 0; i < kDH / 4; i++) ((float4*)qreg)[i] = qrow[i];
    }
    float m = -1e30f, l = 0.f;
    float accv[kDH];
#pragma unroll
    for (int d = 0; d < kDH; d++) accv[d] = 0.f;
    const float scale = 0.125f;

    for (int j = 0; j < kW; j++) {
        const float* kj = ks + (size_t)j * kDH;
        float s0 = 0, s1 = 0, s2 = 0, s3 = 0;
#pragma unroll
        for (int d = 0; d < kDH; d += 4) {
            s0 += qreg[d + 0] * kj[d + 0];
            s1 += qreg[d + 1] * kj[d + 1];
            s2 += qreg[d + 2] * kj[d + 2];
            s3 += qreg[d + 3] * kj[d + 3];
        }
        float s = (s0 + s1 + s2 + s3) * scale;
        float mn = fmaxf(m, s);
        float corr = __expf(m - mn);
        float p = __expf(s - mn);
        l = l * corr + p;
        const float* vj = vs + (size_t)j * kDH;
#pragma unroll
        for (int d = 0; d < kDH; d++) accv[d] = accv[d] * corr + p * vj[d];
        m = mn;
    }
    float inv = 1.0f / l;
    float* orow = attnout + ((size_t)b * kS + sq) * kD + h * kDH;
#pragma unroll
    for (int d = 0; d < kDH; d++) atomicAdd(orow + d, accv[d] * inv);
    atomicAdd(cnt + ((size_t)b * kH + h) * kS + sq, 1.0f);
}

// ---------------- scatter-mean divide ----------------
__global__ void divcnt_kernel(float* __restrict__ attn, const float* __restrict__ cnt) {
    int idx = blockIdx.x * blockDim.x + threadIdx.x;
    if (idx >= kB * kS * kD) return;
    int d = idx % kD;
    int h = d >> 6;
    int s = (idx / kD) % kS;
    int b = idx / (kD * kS);
    float c = cnt[((size_t)b * kH + h) * kS + s];
    attn[idx] = attn[idx] / fmaxf(c, 1.0f);
}

// ---------------- output heads ----------------
__global__ void head_kernel(const float* __restrict__ hln,
                            const float* __restrict__ Wm, const float* __restrict__ bm,
                            const float* __restrict__ Ws, const float* __restrict__ bsd,
                            float* __restrict__ out) {
    int warp = (blockIdx.x * blockDim.x + threadIdx.x) >> 5;
    int lane = threadIdx.x & 31;
    if (warp >= kB * kSF) return;
    int b = warp / kSF, sf = warp % kSF;
    const float* row = hln + ((size_t)b * kS + kSP + sf) * kD;
    float mdot = 0.f, sdot = 0.f;
    for (int d = lane; d < kD; d += 32) {
        float x = row[d];
        mdot += x * Wm[d];
        sdot += x * Ws[d];
    }
#pragma unroll
    for (int o = 16; o; o >>= 1) {
        mdot += __shfl_xor_sync(0xffffffffu, mdot, o);
        sdot += __shfl_xor_sync(0xffffffffu, sdot, o);
    }
    if (lane == 0) {
        out[warp] = mdot + bm[0];
        float ls = sdot + bsd[0];
        float sp = fmaxf(ls, 0.f) + log1pf(__expf(-fabsf(ls)));
        out[(size_t)kB * kSF + warp] = 0.01f + 0.99f * sp;
    }
}

// ---------------- host orchestration ----------------
static void launch_gemm(const float* A, const float* Bm, const float* bias,
                        const float* res, float* C, int M, int N, int K, int act) {
    dim3 grid(N / TBN, M / TBM);
    sgemm_kernel<<<grid, 256>>>(A, Bm, bias, res, C, M, N, K, act);
}

extern "C" void kernel_launch(void* const* d_in, const int* in_sizes, int n_in,
                              void* d_out, int out_size) {
    const float* past_x   = (const float*)d_in[0];
    const float* past_y   = (const float*)d_in[1];
    const float* future_x = (const float*)d_in[2];
    const float* W_emb    = (const float*)d_in[3];
    const float* b_emb    = (const float*)d_in[4];
    const float* ln1_g    = (const float*)d_in[5];
    const float* ln1_b    = (const float*)d_in[6];
    const float* Wq       = (const float*)d_in[7];
    const float* Wk       = (const float*)d_in[8];
    const float* Wv       = (const float*)d_in[9];
    const float* Wo       = (const float*)d_in[10];
    const float* means    = (const float*)d_in[11];
    const float* ln2_g    = (const float*)d_in[12];
    const float* ln2_b    = (const float*)d_in[13];
    const float* W1       = (const float*)d_in[14];
    const float* b1       = (const float*)d_in[15];
    const float* W2       = (const float*)d_in[16];
    const float* b2       = (const float*)d_in[17];
    const float* lnf_g    = (const float*)d_in[18];
    const float* lnf_b    = (const float*)d_in[19];
    const float* W_mean   = (const float*)d_in[20];
    const float* b_mean   = (const float*)d_in[21];
    const float* W_std    = (const float*)d_in[22];
    const float* b_std    = (const float*)d_in[23];

    void *ph, *pln, *pq, *pk, *pv, *pattn, *pffn, *pscores, *pcnt, *piq, *pik;
    cudaGetSymbolAddress(&ph, g_h);
    cudaGetSymbolAddress(&pln, g_ln);
    cudaGetSymbolAddress(&pq, g_q);
    cudaGetSymbolAddress(&pk, g_k);
    cudaGetSymbolAddress(&pv, g_v);
    cudaGetSymbolAddress(&pattn, g_attn);
    cudaGetSymbolAddress(&pffn, g_ffn);
    cudaGetSymbolAddress(&pscores, g_scores);
    cudaGetSymbolAddress(&pcnt, g_cnt);
    cudaGetSymbolAddress(&piq, g_iq);
    cudaGetSymbolAddress(&pik, g_ik);
    float* h    = (float*)ph;
    float* ln   = (float*)pln;
    float* q    = (float*)pq;
    float* k    = (float*)pk;
    float* v    = (float*)pv;
    float* attn = (float*)pattn;
    float* ffn  = (float*)pffn;
    float* scr  = (float*)pscores;
    float* cnt  = (float*)pcnt;
    int*   iq   = (int*)piq;
    int*   ik   = (int*)pik;

    const int attn_smem = 2 * kW * kDH * (int)sizeof(float);  // 64 KB
    cudaFuncSetAttribute(attn_kernel, cudaFuncAttributeMaxDynamicSharedMemorySize, attn_smem);

    {
        int total = kB * kS * kD;
        embed_kernel<<<(total + 255) / 256, 256>>>(past_x, past_y, future_x, W_emb, b_emb, h);
    }

    for (int l = 0; l < kL; l++) {
        const float* mns = means + (size_t)l * kH * kC * kDH;
        // --- attention block ---
        ln_kernel<<<kM, 128>>>(h, ln, ln1_g + (size_t)l * kD, ln1_b + (size_t)l * kD);
        launch_gemm(ln, Wq + (size_t)l * kD * kD, nullptr, nullptr, q, kM, kD, kD, 0);
        launch_gemm(ln, Wk + (size_t)l * kD * kD, nullptr, nullptr, k, kM, kD, kD, 0);
        launch_gemm(ln, Wv + (size_t)l * kD * kD, nullptr, nullptr, v, kM, kD, kD, 0);

        score_kernel<<<kM, 256>>>(q, mns, scr);
        topk_kernel<<<kB * kH * kC, 1024>>>(scr, iq);
        score_kernel<<<kM, 256>>>(k, mns, scr);
        topk_kernel<<<kB * kH * kC, 1024>>>(scr, ik);

        cudaMemsetAsync(attn, 0, (size_t)kB * kS * kD * sizeof(float), 0);
        cudaMemsetAsync(cnt, 0, (size_t)kB * kH * kS * sizeof(float), 0);
        attn_kernel<<<kB * kH * kC, 128, attn_smem>>>(q, k, v, iq, ik, attn, cnt);
        {
            int total = kB * kS * kD;
            divcnt_kernel<<<(total + 255) / 256, 256>>>(attn, cnt);
        }
        // h = h + attn @ Wo
        launch_gemm(attn, Wo + (size_t)l * kD * kD, nullptr, h, h, kM, kD, kD, 0);

        // --- FFN block ---
        ln_kernel<<<kM, 128>>>(h, ln, ln2_g + (size_t)l * kD, ln2_b + (size_t)l * kD);
        launch_gemm(ln, W1 + (size_t)l * kD * kFF, b1 + (size_t)l * kFF, nullptr, ffn, kM, kFF, kD, 1);
        launch_gemm(ffn, W2 + (size_t)l * kFF * kD, b2 + (size_t)l * kD, h, h, kM, kD, kFF, 0);
    }

    ln_kernel<<<kM, 128>>>(h, ln, lnf_g, lnf_b);
    {
        int warps = kB * kSF;
        int threads = warps * 32;
        head_kernel<<<(threads + 255) / 256, 256>>>(ln, W_mean, b_mean, W_std, b_std, (float*)d_out);
    }
}

// round 9
// speedup vs baseline: 1.1032x; 1.0092x over previous
#include <cuda_runtime.h>
#include <cstdint>
#include <cstddef>

// ---------------- problem dims ----------------
#define kB   8
#define kSP  1024
#define kSF  1024
#define kS   2048
#define kXD  6
#define kD   512
#define kL   4
#define kH   8
#define kW   128
#define kDH  64
#define kC   16
#define kFF  2048
#define kM   (kB * kS)          // 16384 rows

typedef unsigned long long u64;

// ---------------- scratch (__device__ globals; no runtime alloc) ----------------
__device__ float g_h   [(size_t)kB * kS * kD];
__device__ float g_ln  [(size_t)kB * kS * kD];
__device__ float g_q   [(size_t)kB * kS * kD];
__device__ float g_k   [(size_t)kB * kS * kD];
__device__ float g_v   [(size_t)kB * kS * kD];
__device__ float g_attn[(size_t)kB * kS * kD];
__device__ float g_ffn [(size_t)kB * kS * kFF];
__device__ float g_scores[(size_t)kB * kH * kC * kS];
__device__ float g_cnt [(size_t)kB * kH * kS];
__device__ int   g_iq  [(size_t)kB * kH * kC * kW];
__device__ int   g_ik  [(size_t)kB * kH * kC * kW];

// ---------------- helpers ----------------
__device__ __forceinline__ float gelu_tanh(float x) {
    float x3 = x * x * x;
    return 0.5f * x * (1.0f + tanhf(0.7978845608028654f * (x + 0.044715f * x3)));
}

__device__ __forceinline__ uint32_t smem_u32(const void* p) {
    uint32_t a;
    asm("{ .reg .u64 t; cvta.to.shared.u64 t, %1; cvt.u32.u64 %0, t; }" : "=r"(a) : "l"(p));
    return a;
}

__device__ __forceinline__ void cp_async16(uint32_t dst, const void* src) {
    asm volatile("cp.async.cg.shared.global [%0], [%1], 16;" :: "r"(dst), "l"(src) : "memory");
}
__device__ __forceinline__ void cp_commit() { asm volatile("cp.async.commit_group;" ::: "memory"); }
__device__ __forceinline__ void cp_wait0()  { asm volatile("cp.async.wait_group 0;" ::: "memory"); }

// packed fp32x2 helpers (SASS FFMA2 — each lane is exact IEEE fp32 fma.rn)
__device__ __forceinline__ u64 splat2(float x) {
    u64 r; asm("mov.b64 %0, {%1, %1};" : "=l"(r) : "f"(x)); return r;
}
__device__ __forceinline__ void ffma2(u64& c, u64 a, u64 b) {
    asm("fma.rn.f32x2 %0, %1, %2, %0;" : "+l"(c) : "l"(a), "l"(b));
}
__device__ __forceinline__ void unpack2(u64 v, float& lo, float& hi) {
    asm("mov.b64 {%0, %1}, %2;" : "=f"(lo), "=f"(hi) : "l"(v));
}

// ---------------- fp32 SGEMM, TBK=16, cp.async double-buffered, FFMA2 core ----------------
// Per-output FMA order identical to the R1/R8 kernel: k ascending, serial;
// each f32x2 lane is an exact fp32 fma.rn -> bit-identical results.
#define TBM 128
#define TBN 128
#define TBK 16
__global__ __launch_bounds__(256, 2) void sgemm_kernel(
    const float* __restrict__ A, const float* __restrict__ Bm,
    const float* __restrict__ bias, const float* __restrict__ res,
    float* __restrict__ Cm, int M, int N, int K, int act) {
    __shared__ float As[2][TBK][TBM];
    __shared__ float Bs[2][TBK][TBN];
    int tid = threadIdx.x;
    int bx = blockIdx.x, by = blockIdx.y;
    int tx = tid % 16, ty = tid / 16;
    const float* Ab = A + (size_t)by * TBM * K;
    const float* Bb = Bm + (size_t)bx * TBN;

    // packed accumulators: accp[ip][j] holds rows (ty*8+2ip, ty*8+2ip+1), col tx*8+j
    u64 accp[4][8];
#pragma unroll
    for (int ip = 0; ip < 4; ip++)
#pragma unroll
        for (int j = 0; j < 8; j++) accp[ip][j] = 0ull;

    // load mapping
    int aRow = tid >> 1, aCol = (tid & 1) * 8;       // A: 128 rows x 16 cols, 2 float4/thread
    int bRow = tid >> 5, bCol = (tid & 31) * 4;      // B: rows bRow and bRow+8, 2 cp.async/thread

    uint32_t bs_base = smem_u32(&Bs[0][0][0]);
    const float* Aptr = Ab + (size_t)aRow * K + aCol;

    // prologue: fill buffer 0 with k-block 0
    {
        cp_async16(bs_base + ((size_t)(0 * TBK + bRow) * TBN + bCol) * 4,
                   Bb + (size_t)bRow * N + bCol);
        cp_async16(bs_base + ((size_t)(0 * TBK + bRow + 8) * TBN + bCol) * 4,
                   Bb + (size_t)(bRow + 8) * N + bCol);
        cp_commit();
        float4 a0 = *(const float4*)(Aptr);
        float4 a1 = *(const float4*)(Aptr + 4);
        As[0][aCol + 0][aRow] = a0.x; As[0][aCol + 1][aRow] = a0.y;
        As[0][aCol + 2][aRow] = a0.z; As[0][aCol + 3][aRow] = a0.w;
        As[0][aCol + 4][aRow] = a1.x; As[0][aCol + 5][aRow] = a1.y;
        As[0][aCol + 6][aRow] = a1.z; As[0][aCol + 7][aRow] = a1.w;
        cp_wait0();
    }
    __syncthreads();

    int nk = K / TBK;
    for (int kb = 0; kb < nk; kb++) {
        int cur = kb & 1, nxt = cur ^ 1;
        float4 a0, a1;
        bool pf = (kb + 1 < nk);
        if (pf) {
            int k0 = (kb + 1) * TBK;
            cp_async16(bs_base + ((size_t)(nxt * TBK + bRow) * TBN + bCol) * 4,
                       Bb + (size_t)(k0 + bRow) * N + bCol);
            cp_async16(bs_base + ((size_t)(nxt * TBK + bRow + 8) * TBN + bCol) * 4,
                       Bb + (size_t)(k0 + bRow + 8) * N + bCol);
            cp_commit();
            a0 = *(const float4*)(Aptr + k0);
            a1 = *(const float4*)(Aptr + k0 + 4);
        }
#pragma unroll
        for (int k = 0; k < TBK; k++) {
            // A rows: float4 pair reinterpreted as 2x f32x2 (adjacent rows) — no packing cost
            u64 ap[4];
            *(float4*)(&ap[0]) = *(const float4*)(&As[cur][k][ty * 8 + 0]);
            *(float4*)(&ap[2]) = *(const float4*)(&As[cur][k][ty * 8 + 4]);
            // B cols: load then splat each into both lanes
            float br[8];
            *(float4*)(br + 0) = *(const float4*)(&Bs[cur][k][tx * 8 + 0]);
            *(float4*)(br + 4) = *(const float4*)(&Bs[cur][k][tx * 8 + 4]);
            u64 bd[8];
#pragma unroll
            for (int j = 0; j < 8; j++) bd[j] = splat2(br[j]);
#pragma unroll
            for (int ip = 0; ip < 4; ip++)
#pragma unroll
                for (int j = 0; j < 8; j++) ffma2(accp[ip][j], ap[ip], bd[j]);
        }
        if (pf) {
            As[nxt][aCol + 0][aRow] = a0.x; As[nxt][aCol + 1][aRow] = a0.y;
            As[nxt][aCol + 2][aRow] = a0.z; As[nxt][aCol + 3][aRow] = a0.w;
            As[nxt][aCol + 4][aRow] = a1.x; As[nxt][aCol + 5][aRow] = a1.y;
            As[nxt][aCol + 6][aRow] = a1.z; As[nxt][aCol + 7][aRow] = a1.w;
            cp_wait0();
        }
        __syncthreads();
    }

    // epilogue (identical numerics to R1/R8)
#pragma unroll
    for (int ip = 0; ip < 4; ip++) {
#pragma unroll
        for (int half = 0; half < 2; half++) {
            int i = ip * 2 + half;
            int row = by * TBM + ty * 8 + i;
            int col0 = bx * TBN + tx * 8;
            float* crow = Cm + (size_t)row * N + col0;
            const float* rrow = res ? res + (size_t)row * N + col0 : nullptr;
#pragma unroll
            for (int j = 0; j < 8; j++) {
                float lo, hi;
                unpack2(accp[ip][j], lo, hi);
                float v = half ? hi : lo;
                if (bias) v += bias[col0 + j];
                if (rrow) v += rrow[j];
                if (act) v = gelu_tanh(v);
                crow[j] = v;
            }
        }
    }
}

// ---------------- embedding ----------------
__global__ void embed_kernel(const float* __restrict__ past_x,
                             const float* __restrict__ past_y,
                             const float* __restrict__ future_x,
                             const float* __restrict__ W_emb,
                             const float* __restrict__ b_emb,
                             float* __restrict__ h) {
    int idx = blockIdx.x * blockDim.x + threadIdx.x;
    if (idx >= kB * kS * kD) return;
    int d = idx % kD;
    int s = (idx / kD) % kS;
    int b = idx / (kD * kS);
    float feat[kXD + 1];
    if (s < kSP) {
#pragma unroll
        for (int j = 0; j < kXD; j++) feat[j] = past_x[((size_t)b * kSP + s) * kXD + j];
        feat[kXD] = past_y[(size_t)b * kSP + s];
    } else {
        int sf = s - kSP;
#pragma unroll
        for (int j = 0; j < kXD; j++) feat[j] = future_x[((size_t)b * kSF + sf) * kXD + j];
        feat[kXD] = past_y[(size_t)b * kSP + (kSP - 1)];
    }
    float acc = b_emb[d];
#pragma unroll
    for (int j = 0; j < kXD + 1; j++) acc += feat[j] * W_emb[(size_t)j * kD + d];
    h[idx] = acc;
}

// ---------------- layernorm (block per row, 128 threads) ----------------
__global__ void ln_kernel(const float* __restrict__ x, float* __restrict__ y,
                          const float* __restrict__ g, const float* __restrict__ bb) {
    __shared__ float red[8];
    int row = blockIdx.x;
    int t = threadIdx.x;
    const float4 xv = ((const float4*)(x + (size_t)row * kD))[t];
    float s = xv.x + xv.y + xv.z + xv.w;
#pragma unroll
    for (int o = 16; o; o >>= 1) s += __shfl_xor_sync(0xffffffffu, s, o);
    if ((t & 31) == 0) red[t >> 5] = s;
    __syncthreads();
    float mean = (red[0] + red[1] + red[2] + red[3]) * (1.0f / kD);
    float dx = xv.x - mean, dy = xv.y - mean, dz = xv.z - mean, dw = xv.w - mean;
    float s2 = dx * dx + dy * dy + dz * dz + dw * dw;
#pragma unroll
    for (int o = 16; o; o >>= 1) s2 += __shfl_xor_sync(0xffffffffu, s2, o);
    if ((t & 31) == 0) red[4 + (t >> 5)] = s2;
    __syncthreads();
    float var = (red[4] + red[5] + red[6] + red[7]) * (1.0f / kD);
    float rstd = rsqrtf(var + 1e-5f);
    const float4 gg = ((const float4*)g)[t];
    const float4 bv = ((const float4*)bb)[t];
    float4 o4;
    o4.x = dx * rstd * gg.x + bv.x;
    o4.y = dy * rstd * gg.y + bv.y;
    o4.z = dz * rstd * gg.z + bv.z;
    o4.w = dw * rstd * gg.w + bv.w;
    ((float4*)(y + (size_t)row * kD))[t] = o4;
}

// ---------------- routing scores ----------------
__global__ void score_kernel(const float* __restrict__ qk,
                             const float* __restrict__ means,
                             float* __restrict__ scores) {
    int bs = blockIdx.x;
    int b = bs / kS, s = bs % kS;
    int h = threadIdx.x >> 5, lane = threadIdx.x & 31;
    const float* qrow = qk + (size_t)bs * kD + h * kDH;
    float qa = qrow[lane], qb = qrow[lane + 32];
    float nrm = qa * qa + qb * qb;
#pragma unroll
    for (int o = 16; o; o >>= 1) nrm += __shfl_xor_sync(0xffffffffu, nrm, o);
    float rn = rsqrtf(nrm + 1e-8f);
#pragma unroll
    for (int c = 0; c < kC; c++) {
        const float* mrow = means + ((size_t)h * kC + c) * kDH;
        float p = qa * mrow[lane] + qb * mrow[lane + 32];
#pragma unroll
        for (int o = 16; o; o >>= 1) p += __shfl_xor_sync(0xffffffffu, p, o);
        if (lane == 0)
            scores[(((size_t)b * kH + h) * kC + c) * kS + s] = p * rn;
    }
}

// ---------------- top-W via bitonic sort ----------------
__global__ void topk_kernel(const float* __restrict__ scores, int* __restrict__ idxout) {
    __shared__ unsigned long long keys[kS];
    int blk = blockIdx.x;
    const float* sp = scores + (size_t)blk * kS;
    for (int i = threadIdx.x; i < kS; i += blockDim.x) {
        unsigned u = __float_as_uint(sp[i]);
        u = (u & 0x80000000u) ? ~u : (u | 0x80000000u);
        keys[i] = ((unsigned long long)u << 32) | (unsigned)i;
    }
    __syncthreads();
    for (int k = 2; k <= kS; k <<= 1) {
        for (int j = k >> 1; j > 0; j >>= 1) {
            for (int i = threadIdx.x; i < kS; i += blockDim.x) {
                int ixj = i ^ j;
                if (ixj > i) {
                    unsigned long long a = keys[i], b = keys[ixj];
                    bool up = ((i & k) == 0);
                    bool sw = up ? (a < b) : (a > b);
                    if (sw) { keys[i] = b; keys[ixj] = a; }
                }
            }
            __syncthreads();
        }
    }
    if (threadIdx.x < kW)
        idxout[(size_t)blk * kW + threadIdx.x] = (int)(keys[threadIdx.x] & 0xffffffffu);
}

// ---------------- within-cluster attention + scatter-add ----------------
__global__ __launch_bounds__(128) void attn_kernel(
    const float* __restrict__ q, const float* __restrict__ k, const float* __restrict__ v,
    const int* __restrict__ iq, const int* __restrict__ ik,
    float* __restrict__ attnout, float* __restrict__ cnt) {
    int blk = blockIdx.x;
    int h = (blk / kC) % kH;
    int b = blk / (kC * kH);
    extern __shared__ float smem[];
    float* ks = smem;
    float* vs = smem + kW * kDH;
    int t = threadIdx.x;
    const int* ikp = ik + (size_t)blk * kW;
    const int* iqp = iq + (size_t)blk * kW;
    {
        int sk = ikp[t];
        const float4* krow = (const float4*)(k + ((size_t)b * kS + sk) * kD + h * kDH);
        const float4* vrow = (const float4*)(v + ((size_t)b * kS + sk) * kD + h * kDH);
        float4* ksr = (float4*)(ks + (size_t)t * kDH);
        float4* vsr = (float4*)(vs + (size_t)t * kDH);
#pragma unroll
        for (int i = 0; i < kDH / 4; i++) { ksr[i] = krow[i]; vsr[i] = vrow[i]; }
    }
    __syncthreads();
    int sq = iqp[t];
    float qreg[kDH];
    {
        const float4* qrow = (const float4*)(q + ((size_t)b * kS + sq) * kD + h * kDH);
#pragma unroll
        for (int i = 0; i < kDH / 4; i++) ((float4*)qreg)[i] = qrow[i];
    }
    float m = -1e30f, l = 0.f;
    float accv[kDH];
#pragma unroll
    for (int d = 0; d < kDH; d++) accv[d] = 0.f;
    const float scale = 0.125f;

    for (int j = 0; j < kW; j++) {
        const float* kj = ks + (size_t)j * kDH;
        float s0 = 0, s1 = 0, s2 = 0, s3 = 0;
#pragma unroll
        for (int d = 0; d < kDH; d += 4) {
            s0 += qreg[d + 0] * kj[d + 0];
            s1 += qreg[d + 1] * kj[d + 1];
            s2 += qreg[d + 2] * kj[d + 2];
            s3 += qreg[d + 3] * kj[d + 3];
        }
        float s = (s0 + s1 + s2 + s3) * scale;
        float mn = fmaxf(m, s);
        float corr = __expf(m - mn);
        float p = __expf(s - mn);
        l = l * corr + p;
        const float* vj = vs + (size_t)j * kDH;
#pragma unroll
        for (int d = 0; d < kDH; d++) accv[d] = accv[d] * corr + p * vj[d];
        m = mn;
    }
    float inv = 1.0f / l;
    float* orow = attnout + ((size_t)b * kS + sq) * kD + h * kDH;
#pragma unroll
    for (int d = 0; d < kDH; d++) atomicAdd(orow + d, accv[d] * inv);
    atomicAdd(cnt + ((size_t)b * kH + h) * kS + sq, 1.0f);
}

// ---------------- scatter-mean divide ----------------
__global__ void divcnt_kernel(float* __restrict__ attn, const float* __restrict__ cnt) {
    int idx = blockIdx.x * blockDim.x + threadIdx.x;
    if (idx >= kB * kS * kD) return;
    int d = idx % kD;
    int h = d >> 6;
    int s = (idx / kD) % kS;
    int b = idx / (kD * kS);
    float c = cnt[((size_t)b * kH + h) * kS + s];
    attn[idx] = attn[idx] / fmaxf(c, 1.0f);
}

// ---------------- output heads ----------------
__global__ void head_kernel(const float* __restrict__ hln,
                            const float* __restrict__ Wm, const float* __restrict__ bm,
                            const float* __restrict__ Ws, const float* __restrict__ bsd,
                            float* __restrict__ out) {
    int warp = (blockIdx.x * blockDim.x + threadIdx.x) >> 5;
    int lane = threadIdx.x & 31;
    if (warp >= kB * kSF) return;
    int b = warp / kSF, sf = warp % kSF;
    const float* row = hln + ((size_t)b * kS + kSP + sf) * kD;
    float mdot = 0.f, sdot = 0.f;
    for (int d = lane; d < kD; d += 32) {
        float x = row[d];
        mdot += x * Wm[d];
        sdot += x * Ws[d];
    }
#pragma unroll
    for (int o = 16; o; o >>= 1) {
        mdot += __shfl_xor_sync(0xffffffffu, mdot, o);
        sdot += __shfl_xor_sync(0xffffffffu, sdot, o);
    }
    if (lane == 0) {
        out[warp] = mdot + bm[0];
        float ls = sdot + bsd[0];
        float sp = fmaxf(ls, 0.f) + log1pf(__expf(-fabsf(ls)));
        out[(size_t)kB * kSF + warp] = 0.01f + 0.99f * sp;
    }
}

// ---------------- host orchestration ----------------
static void launch_gemm(const float* A, const float* Bm, const float* bias,
                        const float* res, float* C, int M, int N, int K, int act) {
    dim3 grid(N / TBN, M / TBM);
    sgemm_kernel<<<grid, 256>>>(A, Bm, bias, res, C, M, N, K, act);
}

extern "C" void kernel_launch(void* const* d_in, const int* in_sizes, int n_in,
                              void* d_out, int out_size) {
    const float* past_x   = (const float*)d_in[0];
    const float* past_y   = (const float*)d_in[1];
    const float* future_x = (const float*)d_in[2];
    const float* W_emb    = (const float*)d_in[3];
    const float* b_emb    = (const float*)d_in[4];
    const float* ln1_g    = (const float*)d_in[5];
    const float* ln1_b    = (const float*)d_in[6];
    const float* Wq       = (const float*)d_in[7];
    const float* Wk       = (const float*)d_in[8];
    const float* Wv       = (const float*)d_in[9];
    const float* Wo       = (const float*)d_in[10];
    const float* means    = (const float*)d_in[11];
    const float* ln2_g    = (const float*)d_in[12];
    const float* ln2_b    = (const float*)d_in[13];
    const float* W1       = (const float*)d_in[14];
    const float* b1       = (const float*)d_in[15];
    const float* W2       = (const float*)d_in[16];
    const float* b2       = (const float*)d_in[17];
    const float* lnf_g    = (const float*)d_in[18];
    const float* lnf_b    = (const float*)d_in[19];
    const float* W_mean   = (const float*)d_in[20];
    const float* b_mean   = (const float*)d_in[21];
    const float* W_std    = (const float*)d_in[22];
    const float* b_std    = (const float*)d_in[23];

    void *ph, *pln, *pq, *pk, *pv, *pattn, *pffn, *pscores, *pcnt, *piq, *pik;
    cudaGetSymbolAddress(&ph, g_h);
    cudaGetSymbolAddress(&pln, g_ln);
    cudaGetSymbolAddress(&pq, g_q);
    cudaGetSymbolAddress(&pk, g_k);
    cudaGetSymbolAddress(&pv, g_v);
    cudaGetSymbolAddress(&pattn, g_attn);
    cudaGetSymbolAddress(&pffn, g_ffn);
    cudaGetSymbolAddress(&pscores, g_scores);
    cudaGetSymbolAddress(&pcnt, g_cnt);
    cudaGetSymbolAddress(&piq, g_iq);
    cudaGetSymbolAddress(&pik, g_ik);
    float* h    = (float*)ph;
    float* ln   = (float*)pln;
    float* q    = (float*)pq;
    float* k    = (float*)pk;
    float* v    = (float*)pv;
    float* attn = (float*)pattn;
    float* ffn  = (float*)pffn;
    float* scr  = (float*)pscores;
    float* cnt  = (float*)pcnt;
    int*   iq   = (int*)piq;
    int*   ik   = (int*)pik;

    const int attn_smem = 2 * kW * kDH * (int)sizeof(float);  // 64 KB
    cudaFuncSetAttribute(attn_kernel, cudaFuncAttributeMaxDynamicSharedMemorySize, attn_smem);

    {
        int total = kB * kS * kD;
        embed_kernel<<<(total + 255) / 256, 256>>>(past_x, past_y, future_x, W_emb, b_emb, h);
    }

    for (int l = 0; l < kL; l++) {
        const float* mns = means + (size_t)l * kH * kC * kDH;
        // --- attention block ---
        ln_kernel<<<kM, 128>>>(h, ln, ln1_g + (size_t)l * kD, ln1_b + (size_t)l * kD);
        launch_gemm(ln, Wq + (size_t)l * kD * kD, nullptr, nullptr, q, kM, kD, kD, 0);
        launch_gemm(ln, Wk + (size_t)l * kD * kD, nullptr, nullptr, k, kM, kD, kD, 0);
        launch_gemm(ln, Wv + (size_t)l * kD * kD, nullptr, nullptr, v, kM, kD, kD, 0);

        score_kernel<<<kM, 256>>>(q, mns, scr);
        topk_kernel<<<kB * kH * kC, 1024>>>(scr, iq);
        score_kernel<<<kM, 256>>>(k, mns, scr);
        topk_kernel<<<kB * kH * kC, 1024>>>(scr, ik);

        cudaMemsetAsync(attn, 0, (size_t)kB * kS * kD * sizeof(float), 0);
        cudaMemsetAsync(cnt, 0, (size_t)kB * kH * kS * sizeof(float), 0);
        attn_kernel<<<kB * kH * kC, 128, attn_smem>>>(q, k, v, iq, ik, attn, cnt);
        {
            int total = kB * kS * kD;
            divcnt_kernel<<<(total + 255) / 256, 256>>>(attn, cnt);
        }
        // h = h + attn @ Wo
        launch_gemm(attn, Wo + (size_t)l * kD * kD, nullptr, h, h, kM, kD, kD, 0);

        // --- FFN block ---
        ln_kernel<<<kM, 128>>>(h, ln, ln2_g + (size_t)l * kD, ln2_b + (size_t)l * kD);
        launch_gemm(ln, W1 + (size_t)l * kD * kFF, b1 + (size_t)l * kFF, nullptr, ffn, kM, kFF, kD, 1);
        launch_gemm(ffn, W2 + (size_t)l * kFF * kD, b2 + (size_t)l * kD, h, h, kM, kD, kFF, 0);
    }

    ln_kernel<<<kM, 128>>>(h, ln, lnf_g, lnf_b);
    {
        int warps = kB * kSF;
        int threads = warps * 32;
        head_kernel<<<(threads + 255) / 256, 256>>>(ln, W_mean, b_mean, W_std, b_std, (float*)d_out);
    }
}

// round 10
// speedup vs baseline: 1.1099x; 1.0061x over previous
#include <cuda_runtime.h>
#include <cstdint>
#include <cstddef>

// ---------------- problem dims ----------------
#define kB   8
#define kSP  1024
#define kSF  1024
#define kS   2048
#define kXD  6
#define kD   512
#define kL   4
#define kH   8
#define kW   128
#define kDH  64
#define kC   16
#define kFF  2048
#define kM   (kB * kS)          // 16384 rows
#define kNBHC (kB * kH * kC)    // 1024

typedef unsigned long long u64;

// ---------------- scratch (__device__ globals; no runtime alloc) ----------------
__device__ float g_h   [(size_t)kB * kS * kD];
__device__ float g_ln  [(size_t)kB * kS * kD];
__device__ float g_q   [(size_t)kB * kS * kD];
__device__ float g_k   [(size_t)kB * kS * kD];
__device__ float g_v   [(size_t)kB * kS * kD];
// attn accumulator + cnt merged: one memset covers both
__device__ float g_attncnt[(size_t)kB * kS * kD + (size_t)kB * kH * kS];
__device__ float g_ffn [(size_t)kB * kS * kFF];
__device__ float g_scores[(size_t)2 * kNBHC * kS];     // [0]=q scores, [1]=k scores
__device__ int   g_idx [(size_t)2 * kNBHC * kW];       // [0]=iq, [1]=ik

// ---------------- helpers ----------------
__device__ __forceinline__ float gelu_tanh(float x) {
    float x3 = x * x * x;
    return 0.5f * x * (1.0f + tanhf(0.7978845608028654f * (x + 0.044715f * x3)));
}

__device__ __forceinline__ uint32_t smem_u32(const void* p) {
    uint32_t a;
    asm("{ .reg .u64 t; cvta.to.shared.u64 t, %1; cvt.u32.u64 %0, t; }" : "=r"(a) : "l"(p));
    return a;
}

__device__ __forceinline__ void cp_async16(uint32_t dst, const void* src) {
    asm volatile("cp.async.cg.shared.global [%0], [%1], 16;" :: "r"(dst), "l"(src) : "memory");
}
__device__ __forceinline__ void cp_commit() { asm volatile("cp.async.commit_group;" ::: "memory"); }
__device__ __forceinline__ void cp_wait0()  { asm volatile("cp.async.wait_group 0;" ::: "memory"); }

// packed fp32x2 helpers (each lane is exact IEEE fp32 fma.rn)
__device__ __forceinline__ u64 splat2(float x) {
    u64 r; asm("mov.b64 %0, {%1, %1};" : "=l"(r) : "f"(x)); return r;
}
__device__ __forceinline__ void ffma2(u64& c, u64 a, u64 b) {
    asm("fma.rn.f32x2 %0, %1, %2, %0;" : "+l"(c) : "l"(a), "l"(b));
}
__device__ __forceinline__ void unpack2(u64 v, float& lo, float& hi) {
    asm("mov.b64 {%0, %1}, %2;" : "=f"(lo), "=f"(hi) : "l"(v));
}

// ---------------- fp32 SGEMM, TBK=16, cp.async double-buffered ----------------
// Per-output FMA order identical to the R1 kernel (serial k ascending).
// Optional acnt: divide A elements by fmax(cnt,1) at load (folds divcnt pass;
// same div.rn.f32 as the old divcnt kernel -> bit-identical values).
#define TBM 128
#define TBN 128
#define TBK 16
__global__ __launch_bounds__(256, 2) void sgemm_kernel(
    const float* __restrict__ A, const float* __restrict__ Bm,
    const float* __restrict__ bias, const float* __restrict__ res,
    const float* __restrict__ acnt,
    float* __restrict__ Cm, int M, int N, int K, int act) {
    __shared__ float As[2][TBK][TBM];
    __shared__ float Bs[2][TBK][TBN];
    int tid = threadIdx.x;
    int bx = blockIdx.x, by = blockIdx.y;
    int tx = tid % 16, ty = tid / 16;
    const float* Ab = A + (size_t)by * TBM * K;
    const float* Bb = Bm + (size_t)bx * TBN;

    u64 accp[4][8];
#pragma unroll
    for (int ip = 0; ip < 4; ip++)
#pragma unroll
        for (int j = 0; j < 8; j++) accp[ip][j] = 0ull;

    int aRow = tid >> 1, aCol = (tid & 1) * 8;
    int bRow = tid >> 5, bCol = (tid & 31) * 4;

    uint32_t bs_base = smem_u32(&Bs[0][0][0]);
    const float* Aptr = Ab + (size_t)aRow * K + aCol;

    // cnt lookup base for this thread's A row (only when acnt != null)
    int grow = by * TBM + aRow;
    int cb = grow / kS, cs = grow % kS;
    const float* cnt_row = acnt ? acnt + ((size_t)cb * kH) * kS + cs : nullptr;

    // prologue: fill buffer 0 with k-block 0
    {
        cp_async16(bs_base + ((size_t)(0 * TBK + bRow) * TBN + bCol) * 4,
                   Bb + (size_t)bRow * N + bCol);
        cp_async16(bs_base + ((size_t)(0 * TBK + bRow + 8) * TBN + bCol) * 4,
                   Bb + (size_t)(bRow + 8) * N + bCol);
        cp_commit();
        float4 a0 = *(const float4*)(Aptr);
        float4 a1 = *(const float4*)(Aptr + 4);
        if (cnt_row) {
            int hh = aCol >> 6;   // k0 = 0
            float c = fmaxf(cnt_row[(size_t)hh * kS], 1.0f);
            a0.x /= c; a0.y /= c; a0.z /= c; a0.w /= c;
            a1.x /= c; a1.y /= c; a1.z /= c; a1.w /= c;
        }
        As[0][aCol + 0][aRow] = a0.x; As[0][aCol + 1][aRow] = a0.y;
        As[0][aCol + 2][aRow] = a0.z; As[0][aCol + 3][aRow] = a0.w;
        As[0][aCol + 4][aRow] = a1.x; As[0][aCol + 5][aRow] = a1.y;
        As[0][aCol + 6][aRow] = a1.z; As[0][aCol + 7][aRow] = a1.w;
        cp_wait0();
    }
    __syncthreads();

    int nk = K / TBK;
    for (int kb = 0; kb < nk; kb++) {
        int cur = kb & 1, nxt = cur ^ 1;
        float4 a0, a1;
        bool pf = (kb + 1 < nk);
        if (pf) {
            int k0 = (kb + 1) * TBK;
            cp_async16(bs_base + ((size_t)(nxt * TBK + bRow) * TBN + bCol) * 4,
                       Bb + (size_t)(k0 + bRow) * N + bCol);
            cp_async16(bs_base + ((size_t)(nxt * TBK + bRow + 8) * TBN + bCol) * 4,
                       Bb + (size_t)(k0 + bRow + 8) * N + bCol);
            cp_commit();
            a0 = *(const float4*)(Aptr + k0);
            a1 = *(const float4*)(Aptr + k0 + 4);
            if (cnt_row) {
                int hh = (k0 + aCol) >> 6;    // all 8 elems within one 64-block
                float c = fmaxf(cnt_row[(size_t)hh * kS], 1.0f);
                a0.x /= c; a0.y /= c; a0.z /= c; a0.w /= c;
                a1.x /= c; a1.y /= c; a1.z /= c; a1.w /= c;
            }
        }
#pragma unroll
        for (int k = 0; k < TBK; k++) {
            u64 ap[4];
            *(float4*)(&ap[0]) = *(const float4*)(&As[cur][k][ty * 8 + 0]);
            *(float4*)(&ap[2]) = *(const float4*)(&As[cur][k][ty * 8 + 4]);
            float br[8];
            *(float4*)(br + 0) = *(const float4*)(&Bs[cur][k][tx * 8 + 0]);
            *(float4*)(br + 4) = *(const float4*)(&Bs[cur][k][tx * 8 + 4]);
            u64 bd[8];
#pragma unroll
            for (int j = 0; j < 8; j++) bd[j] = splat2(br[j]);
#pragma unroll
            for (int ip = 0; ip < 4; ip++)
#pragma unroll
                for (int j = 0; j < 8; j++) ffma2(accp[ip][j], ap[ip], bd[j]);
        }
        if (pf) {
            As[nxt][aCol + 0][aRow] = a0.x; As[nxt][aCol + 1][aRow] = a0.y;
            As[nxt][aCol + 2][aRow] = a0.z; As[nxt][aCol + 3][aRow] = a0.w;
            As[nxt][aCol + 4][aRow] = a1.x; As[nxt][aCol + 5][aRow] = a1.y;
            As[nxt][aCol + 6][aRow] = a1.z; As[nxt][aCol + 7][aRow] = a1.w;
            cp_wait0();
        }
        __syncthreads();
    }

    // epilogue (identical numerics to R1/R8/R9)
#pragma unroll
    for (int ip = 0; ip < 4; ip++) {
#pragma unroll
        for (int half = 0; half < 2; half++) {
            int i = ip * 2 + half;
            int row = by * TBM + ty * 8 + i;
            int col0 = bx * TBN + tx * 8;
            float* crow = Cm + (size_t)row * N + col0;
            const float* rrow = res ? res + (size_t)row * N + col0 : nullptr;
#pragma unroll
            for (int j = 0; j < 8; j++) {
                float lo, hi;
                unpack2(accp[ip][j], lo, hi);
                float v = half ? hi : lo;
                if (bias) v += bias[col0 + j];
                if (rrow) v += rrow[j];
                if (act) v = gelu_tanh(v);
                crow[j] = v;
            }
        }
    }
}

// ---------------- embedding ----------------
__global__ void embed_kernel(const float* __restrict__ past_x,
                             const float* __restrict__ past_y,
                             const float* __restrict__ future_x,
                             const float* __restrict__ W_emb,
                             const float* __restrict__ b_emb,
                             float* __restrict__ h) {
    int idx = blockIdx.x * blockDim.x + threadIdx.x;
    if (idx >= kB * kS * kD) return;
    int d = idx % kD;
    int s = (idx / kD) % kS;
    int b = idx / (kD * kS);
    float feat[kXD + 1];
    if (s < kSP) {
#pragma unroll
        for (int j = 0; j < kXD; j++) feat[j] = past_x[((size_t)b * kSP + s) * kXD + j];
        feat[kXD] = past_y[(size_t)b * kSP + s];
    } else {
        int sf = s - kSP;
#pragma unroll
        for (int j = 0; j < kXD; j++) feat[j] = future_x[((size_t)b * kSF + sf) * kXD + j];
        feat[kXD] = past_y[(size_t)b * kSP + (kSP - 1)];
    }
    float acc = b_emb[d];
#pragma unroll
    for (int j = 0; j < kXD + 1; j++) acc += feat[j] * W_emb[(size_t)j * kD + d];
    h[idx] = acc;
}

// ---------------- layernorm (block per row, 128 threads) ----------------
__global__ void ln_kernel(const float* __restrict__ x, float* __restrict__ y,
                          const float* __restrict__ g, const float* __restrict__ bb) {
    __shared__ float red[8];
    int row = blockIdx.x;
    int t = threadIdx.x;
    const float4 xv = ((const float4*)(x + (size_t)row * kD))[t];
    float s = xv.x + xv.y + xv.z + xv.w;
#pragma unroll
    for (int o = 16; o; o >>= 1) s += __shfl_xor_sync(0xffffffffu, s, o);
    if ((t & 31) == 0) red[t >> 5] = s;
    __syncthreads();
    float mean = (red[0] + red[1] + red[2] + red[3]) * (1.0f / kD);
    float dx = xv.x - mean, dy = xv.y - mean, dz = xv.z - mean, dw = xv.w - mean;
    float s2 = dx * dx + dy * dy + dz * dz + dw * dw;
#pragma unroll
    for (int o = 16; o; o >>= 1) s2 += __shfl_xor_sync(0xffffffffu, s2, o);
    if ((t & 31) == 0) red[4 + (t >> 5)] = s2;
    __syncthreads();
    float var = (red[4] + red[5] + red[6] + red[7]) * (1.0f / kD);
    float rstd = rsqrtf(var + 1e-5f);
    const float4 gg = ((const float4*)g)[t];
    const float4 bv = ((const float4*)bb)[t];
    float4 o4;
    o4.x = dx * rstd * gg.x + bv.x;
    o4.y = dy * rstd * gg.y + bv.y;
    o4.z = dz * rstd * gg.z + bv.z;
    o4.w = dw * rstd * gg.w + bv.w;
    ((float4*)(y + (size_t)row * kD))[t] = o4;
}

// ---------------- routing scores (q and k in one launch) ----------------
__global__ void score2_kernel(const float* __restrict__ q,
                              const float* __restrict__ k,
                              const float* __restrict__ means,
                              float* __restrict__ scores) {
    int gb = blockIdx.x;
    int inst = gb / kM;              // 0: q scores, 1: k scores
    int bs = gb % kM;
    const float* src = inst ? k : q;
    float* dst = scores + (size_t)inst * kNBHC * kS;
    int b = bs / kS, s = bs % kS;
    int h = threadIdx.x >> 5, lane = threadIdx.x & 31;
    const float* qrow = src + (size_t)bs * kD + h * kDH;
    float qa = qrow[lane], qb = qrow[lane + 32];
    float nrm = qa * qa + qb * qb;
#pragma unroll
    for (int o = 16; o; o >>= 1) nrm += __shfl_xor_sync(0xffffffffu, nrm, o);
    float rn = rsqrtf(nrm + 1e-8f);
#pragma unroll
    for (int c = 0; c < kC; c++) {
        const float* mrow = means + ((size_t)h * kC + c) * kDH;
        float p = qa * mrow[lane] + qb * mrow[lane + 32];
#pragma unroll
        for (int o = 16; o; o >>= 1) p += __shfl_xor_sync(0xffffffffu, p, o);
        if (lane == 0)
            dst[(((size_t)b * kH + h) * kC + c) * kS + s] = p * rn;
    }
}

// ---------------- top-W via bitonic sort (q and k halves in one launch) ----------------
__global__ void topk_kernel(const float* __restrict__ scores, int* __restrict__ idxout) {
    __shared__ unsigned long long keys[kS];
    int blk = blockIdx.x;                      // 0..2*kNBHC-1
    const float* sp = scores + (size_t)blk * kS;
    for (int i = threadIdx.x; i < kS; i += blockDim.x) {
        unsigned u = __float_as_uint(sp[i]);
        u = (u & 0x80000000u) ? ~u : (u | 0x80000000u);
        keys[i] = ((unsigned long long)u << 32) | (unsigned)i;
    }
    __syncthreads();
    for (int k = 2; k <= kS; k <<= 1) {
        for (int j = k >> 1; j > 0; j >>= 1) {
            for (int i = threadIdx.x; i < kS; i += blockDim.x) {
                int ixj = i ^ j;
                if (ixj > i) {
                    unsigned long long a = keys[i], b = keys[ixj];
                    bool up = ((i & k) == 0);
                    bool sw = up ? (a < b) : (a > b);
                    if (sw) { keys[i] = b; keys[ixj] = a; }
                }
            }
            __syncthreads();
        }
    }
    if (threadIdx.x < kW)
        idxout[(size_t)blk * kW + threadIdx.x] = (int)(keys[threadIdx.x] & 0xffffffffu);
}

// ---------------- within-cluster attention + scatter-add ----------------
__global__ __launch_bounds__(128) void attn_kernel(
    const float* __restrict__ q, const float* __restrict__ k, const float* __restrict__ v,
    const int* __restrict__ iq, const int* __restrict__ ik,
    float* __restrict__ attnout, float* __restrict__ cnt) {
    int blk = blockIdx.x;
    int h = (blk / kC) % kH;
    int b = blk / (kC * kH);
    extern __shared__ float smem[];
    float* ks = smem;
    float* vs = smem + kW * kDH;
    int t = threadIdx.x;
    const int* ikp = ik + (size_t)blk * kW;
    const int* iqp = iq + (size_t)blk * kW;
    {
        int sk = ikp[t];
        const float4* krow = (const float4*)(k + ((size_t)b * kS + sk) * kD + h * kDH);
        const float4* vrow = (const float4*)(v + ((size_t)b * kS + sk) * kD + h * kDH);
        float4* ksr = (float4*)(ks + (size_t)t * kDH);
        float4* vsr = (float4*)(vs + (size_t)t * kDH);
#pragma unroll
        for (int i = 0; i < kDH / 4; i++) { ksr[i] = krow[i]; vsr[i] = vrow[i]; }
    }
    __syncthreads();
    int sq = iqp[t];
    float qreg[kDH];
    {
        const float4* qrow = (const float4*)(q + ((size_t)b * kS + sq) * kD + h * kDH);
#pragma unroll
        for (int i = 0; i < kDH / 4; i++) ((float4*)qreg)[i] = qrow[i];
    }
    float m = -1e30f, l = 0.f;
    float accv[kDH];
#pragma unroll
    for (int d = 0; d < kDH; d++) accv[d] = 0.f;
    const float scale = 0.125f;

    for (int j = 0; j < kW; j++) {
        const float* kj = ks + (size_t)j * kDH;
        float s0 = 0, s1 = 0, s2 = 0, s3 = 0;
#pragma unroll
        for (int d = 0; d < kDH; d += 4) {
            s0 += qreg[d + 0] * kj[d + 0];
            s1 += qreg[d + 1] * kj[d + 1];
            s2 += qreg[d + 2] * kj[d + 2];
            s3 += qreg[d + 3] * kj[d + 3];
        }
        float s = (s0 + s1 + s2 + s3) * scale;
        float mn = fmaxf(m, s);
        float corr = __expf(m - mn);
        float p = __expf(s - mn);
        l = l * corr + p;
        const float* vj = vs + (size_t)j * kDH;
#pragma unroll
        for (int d = 0; d < kDH; d++) accv[d] = accv[d] * corr + p * vj[d];
        m = mn;
    }
    float inv = 1.0f / l;
    float* orow = attnout + ((size_t)b * kS + sq) * kD + h * kDH;
#pragma unroll
    for (int d = 0; d < kDH; d++) atomicAdd(orow + d, accv[d] * inv);
    atomicAdd(cnt + ((size_t)b * kH + h) * kS + sq, 1.0f);
}

// ---------------- output heads ----------------
__global__ void head_kernel(const float* __restrict__ hln,
                            const float* __restrict__ Wm, const float* __restrict__ bm,
                            const float* __restrict__ Ws, const float* __restrict__ bsd,
                            float* __restrict__ out) {
    int warp = (blockIdx.x * blockDim.x + threadIdx.x) >> 5;
    int lane = threadIdx.x & 31;
    if (warp >= kB * kSF) return;
    int b = warp / kSF, sf = warp % kSF;
    const float* row = hln + ((size_t)b * kS + kSP + sf) * kD;
    float mdot = 0.f, sdot = 0.f;
    for (int d = lane; d < kD; d += 32) {
        float x = row[d];
        mdot += x * Wm[d];
        sdot += x * Ws[d];
    }
#pragma unroll
    for (int o = 16; o; o >>= 1) {
        mdot += __shfl_xor_sync(0xffffffffu, mdot, o);
        sdot += __shfl_xor_sync(0xffffffffu, sdot, o);
    }
    if (lane == 0) {
        out[warp] = mdot + bm[0];
        float ls = sdot + bsd[0];
        float sp = fmaxf(ls, 0.f) + log1pf(__expf(-fabsf(ls)));
        out[(size_t)kB * kSF + warp] = 0.01f + 0.99f * sp;
    }
}

// ---------------- host orchestration ----------------
static void launch_gemm(const float* A, const float* Bm, const float* bias,
                        const float* res, const float* acnt, float* C,
                        int M, int N, int K, int act) {
    dim3 grid(N / TBN, M / TBM);
    sgemm_kernel<<<grid, 256>>>(A, Bm, bias, res, acnt, C, M, N, K, act);
}

extern "C" void kernel_launch(void* const* d_in, const int* in_sizes, int n_in,
                              void* d_out, int out_size) {
    const float* past_x   = (const float*)d_in[0];
    const float* past_y   = (const float*)d_in[1];
    const float* future_x = (const float*)d_in[2];
    const float* W_emb    = (const float*)d_in[3];
    const float* b_emb    = (const float*)d_in[4];
    const float* ln1_g    = (const float*)d_in[5];
    const float* ln1_b    = (const float*)d_in[6];
    const float* Wq       = (const float*)d_in[7];
    const float* Wk       = (const float*)d_in[8];
    const float* Wv       = (const float*)d_in[9];
    const float* Wo       = (const float*)d_in[10];
    const float* means    = (const float*)d_in[11];
    const float* ln2_g    = (const float*)d_in[12];
    const float* ln2_b    = (const float*)d_in[13];
    const float* W1       = (const float*)d_in[14];
    const float* b1       = (const float*)d_in[15];
    const float* W2       = (const float*)d_in[16];
    const float* b2       = (const float*)d_in[17];
    const float* lnf_g    = (const float*)d_in[18];
    const float* lnf_b    = (const float*)d_in[19];
    const float* W_mean   = (const float*)d_in[20];
    const float* b_mean   = (const float*)d_in[21];
    const float* W_std    = (const float*)d_in[22];
    const float* b_std    = (const float*)d_in[23];

    void *ph, *pln, *pq, *pk, *pv, *pac, *pffn, *pscores, *pidx;
    cudaGetSymbolAddress(&ph, g_h);
    cudaGetSymbolAddress(&pln, g_ln);
    cudaGetSymbolAddress(&pq, g_q);
    cudaGetSymbolAddress(&pk, g_k);
    cudaGetSymbolAddress(&pv, g_v);
    cudaGetSymbolAddress(&pac, g_attncnt);
    cudaGetSymbolAddress(&pffn, g_ffn);
    cudaGetSymbolAddress(&pscores, g_scores);
    cudaGetSymbolAddress(&pidx, g_idx);
    float* h    = (float*)ph;
    float* ln   = (float*)pln;
    float* q    = (float*)pq;
    float* k    = (float*)pk;
    float* v    = (float*)pv;
    float* attn = (float*)pac;                               // attn accumulator
    float* cnt  = (float*)pac + (size_t)kB * kS * kD;        // cnt (adjacent)
    float* ffn  = (float*)pffn;
    float* scr  = (float*)pscores;
    int*   iq   = (int*)pidx;                                // first half
    int*   ik   = (int*)pidx + (size_t)kNBHC * kW;           // second half

    const int attn_smem = 2 * kW * kDH * (int)sizeof(float);  // 64 KB
    cudaFuncSetAttribute(attn_kernel, cudaFuncAttributeMaxDynamicSharedMemorySize, attn_smem);

    {
        int total = kB * kS * kD;
        embed_kernel<<<(total + 255) / 256, 256>>>(past_x, past_y, future_x, W_emb, b_emb, h);
    }

    const size_t attncnt_bytes = ((size_t)kB * kS * kD + (size_t)kB * kH * kS) * sizeof(float);

    for (int l = 0; l < kL; l++) {
        const float* mns = means + (size_t)l * kH * kC * kDH;
        // --- attention block ---
        ln_kernel<<<kM, 128>>>(h, ln, ln1_g + (size_t)l * kD, ln1_b + (size_t)l * kD);
        launch_gemm(ln, Wq + (size_t)l * kD * kD, nullptr, nullptr, nullptr, q, kM, kD, kD, 0);
        launch_gemm(ln, Wk + (size_t)l * kD * kD, nullptr, nullptr, nullptr, k, kM, kD, kD, 0);
        launch_gemm(ln, Wv + (size_t)l * kD * kD, nullptr, nullptr, nullptr, v, kM, kD, kD, 0);

        // scores for q and k in one launch; topk for both in one launch
        score2_kernel<<<2 * kM, 256>>>(q, k, mns, scr);
        topk_kernel<<<2 * kNBHC, 1024>>>(scr, (int*)pidx);

        cudaMemsetAsync(attn, 0, attncnt_bytes, 0);
        attn_kernel<<<kNBHC, 128, attn_smem>>>(q, k, v, iq, ik, attn, cnt);

        // h = h + (attn/cnt) @ Wo   (divcnt folded into GEMM A-load)
        launch_gemm(attn, Wo + (size_t)l * kD * kD, nullptr, h, cnt, h, kM, kD, kD, 0);

        // --- FFN block ---
        ln_kernel<<<kM, 128>>>(h, ln, ln2_g + (size_t)l * kD, ln2_b + (size_t)l * kD);
        launch_gemm(ln, W1 + (size_t)l * kD * kFF, b1 + (size_t)l * kFF, nullptr, nullptr, ffn, kM, kFF, kD, 1);
        launch_gemm(ffn, W2 + (size_t)l * kFF * kD, b2 + (size_t)l * kD, h, nullptr, h, kM, kD, kFF, 0);
    }

    ln_kernel<<<kM, 128>>>(h, ln, lnf_g, lnf_b);
    {
        int warps = kB * kSF;
        int threads = warps * 32;
        head_kernel<<<(threads + 255) / 256, 256>>>(ln, W_mean, b_mean, W_std, b_std, (float*)d_out);
    }
}

// round 11
// speedup vs baseline: 1.1329x; 1.0207x over previous
#include <cuda_runtime.h>
#include <cstdint>
#include <cstddef>

// ---------------- problem dims ----------------
#define kB   8
#define kSP  1024
#define kSF  1024
#define kS   2048
#define kXD  6
#define kD   512
#define kL   4
#define kH   8
#define kW   128
#define kDH  64
#define kC   16
#define kFF  2048
#define kM   (kB * kS)          // 16384 rows
#define kNBHC (kB * kH * kC)    // 1024

typedef unsigned long long u64;

// ---------------- scratch (__device__ globals; no runtime alloc) ----------------
__device__ float g_h   [(size_t)kB * kS * kD];
__device__ float g_ln  [(size_t)kB * kS * kD];
__device__ float g_q   [(size_t)kB * kS * kD];
__device__ float g_k   [(size_t)kB * kS * kD];
__device__ float g_v   [(size_t)kB * kS * kD];
// attn accumulator + cnt merged: one memset covers both
__device__ float g_attncnt[(size_t)kB * kS * kD + (size_t)kB * kH * kS];
__device__ float g_ffn [(size_t)kB * kS * kFF];
__device__ float g_scores[(size_t)2 * kNBHC * kS];     // [0]=q scores, [1]=k scores
__device__ int   g_idx [(size_t)2 * kNBHC * kW];       // [0]=iq, [1]=ik

// ---------------- helpers ----------------
__device__ __forceinline__ float gelu_tanh(float x) {
    float x3 = x * x * x;
    return 0.5f * x * (1.0f + tanhf(0.7978845608028654f * (x + 0.044715f * x3)));
}

__device__ __forceinline__ uint32_t smem_u32(const void* p) {
    uint32_t a;
    asm("{ .reg .u64 t; cvta.to.shared.u64 t, %1; cvt.u32.u64 %0, t; }" : "=r"(a) : "l"(p));
    return a;
}

__device__ __forceinline__ void cp_async16(uint32_t dst, const void* src) {
    asm volatile("cp.async.cg.shared.global [%0], [%1], 16;" :: "r"(dst), "l"(src) : "memory");
}
__device__ __forceinline__ void cp_commit() { asm volatile("cp.async.commit_group;" ::: "memory"); }
__device__ __forceinline__ void cp_wait0()  { asm volatile("cp.async.wait_group 0;" ::: "memory"); }

// packed fp32x2 helpers (each lane is exact IEEE fp32 fma.rn)
__device__ __forceinline__ u64 splat2(float x) {
    u64 r; asm("mov.b64 %0, {%1, %1};" : "=l"(r) : "f"(x)); return r;
}
__device__ __forceinline__ void ffma2(u64& c, u64 a, u64 b) {
    asm("fma.rn.f32x2 %0, %1, %2, %0;" : "+l"(c) : "l"(a), "l"(b));
}
__device__ __forceinline__ void unpack2(u64 v, float& lo, float& hi) {
    asm("mov.b64 {%0, %1}, %2;" : "=f"(lo), "=f"(hi) : "l"(v));
}

// ---------------- fp32 GEMM tile body (TBK=16, cp.async double-buffered) ----------------
// Per-output FMA order identical to the R1 kernel (serial k ascending).
#define TBM 128
#define TBN 128
#define TBK 16
__device__ __forceinline__ void gemm_body(
    const float* __restrict__ A, const float* __restrict__ Bm,
    const float* __restrict__ bias, const float* __restrict__ res,
    const float* __restrict__ acnt,
    float* __restrict__ Cm, int M, int N, int K, int act, int bx, int by) {
    __shared__ float As[2][TBK][TBM];
    __shared__ float Bs[2][TBK][TBN];
    int tid = threadIdx.x;
    int tx = tid % 16, ty = tid / 16;
    const float* Ab = A + (size_t)by * TBM * K;
    const float* Bb = Bm + (size_t)bx * TBN;

    u64 accp[4][8];
#pragma unroll
    for (int ip = 0; ip < 4; ip++)
#pragma unroll
        for (int j = 0; j < 8; j++) accp[ip][j] = 0ull;

    int aRow = tid >> 1, aCol = (tid & 1) * 8;
    int bRow = tid >> 5, bCol = (tid & 31) * 4;

    uint32_t bs_base = smem_u32(&Bs[0][0][0]);
    const float* Aptr = Ab + (size_t)aRow * K + aCol;

    // cnt lookup base for this thread's A row (only when acnt != null)
    int grow = by * TBM + aRow;
    int cb = grow / kS, cs = grow % kS;
    const float* cnt_row = acnt ? acnt + ((size_t)cb * kH) * kS + cs : nullptr;

    // prologue: fill buffer 0 with k-block 0
    {
        cp_async16(bs_base + ((size_t)(0 * TBK + bRow) * TBN + bCol) * 4,
                   Bb + (size_t)bRow * N + bCol);
        cp_async16(bs_base + ((size_t)(0 * TBK + bRow + 8) * TBN + bCol) * 4,
                   Bb + (size_t)(bRow + 8) * N + bCol);
        cp_commit();
        float4 a0 = *(const float4*)(Aptr);
        float4 a1 = *(const float4*)(Aptr + 4);
        if (cnt_row) {
            int hh = aCol >> 6;
            float c = fmaxf(cnt_row[(size_t)hh * kS], 1.0f);
            a0.x /= c; a0.y /= c; a0.z /= c; a0.w /= c;
            a1.x /= c; a1.y /= c; a1.z /= c; a1.w /= c;
        }
        As[0][aCol + 0][aRow] = a0.x; As[0][aCol + 1][aRow] = a0.y;
        As[0][aCol + 2][aRow] = a0.z; As[0][aCol + 3][aRow] = a0.w;
        As[0][aCol + 4][aRow] = a1.x; As[0][aCol + 5][aRow] = a1.y;
        As[0][aCol + 6][aRow] = a1.z; As[0][aCol + 7][aRow] = a1.w;
        cp_wait0();
    }
    __syncthreads();

    int nk = K / TBK;
    for (int kb = 0; kb < nk; kb++) {
        int cur = kb & 1, nxt = cur ^ 1;
        float4 a0, a1;
        bool pf = (kb + 1 < nk);
        if (pf) {
            int k0 = (kb + 1) * TBK;
            cp_async16(bs_base + ((size_t)(nxt * TBK + bRow) * TBN + bCol) * 4,
                       Bb + (size_t)(k0 + bRow) * N + bCol);
            cp_async16(bs_base + ((size_t)(nxt * TBK + bRow + 8) * TBN + bCol) * 4,
                       Bb + (size_t)(k0 + bRow + 8) * N + bCol);
            cp_commit();
            a0 = *(const float4*)(Aptr + k0);
            a1 = *(const float4*)(Aptr + k0 + 4);
            if (cnt_row) {
                int hh = (k0 + aCol) >> 6;
                float c = fmaxf(cnt_row[(size_t)hh * kS], 1.0f);
                a0.x /= c; a0.y /= c; a0.z /= c; a0.w /= c;
                a1.x /= c; a1.y /= c; a1.z /= c; a1.w /= c;
            }
        }
#pragma unroll
        for (int k = 0; k < TBK; k++) {
            u64 ap[4];
            *(float4*)(&ap[0]) = *(const float4*)(&As[cur][k][ty * 8 + 0]);
            *(float4*)(&ap[2]) = *(const float4*)(&As[cur][k][ty * 8 + 4]);
            float br[8];
            *(float4*)(br + 0) = *(const float4*)(&Bs[cur][k][tx * 8 + 0]);
            *(float4*)(br + 4) = *(const float4*)(&Bs[cur][k][tx * 8 + 4]);
            u64 bd[8];
#pragma unroll
            for (int j = 0; j < 8; j++) bd[j] = splat2(br[j]);
#pragma unroll
            for (int ip = 0; ip < 4; ip++)
#pragma unroll
                for (int j = 0; j < 8; j++) ffma2(accp[ip][j], ap[ip], bd[j]);
        }
        if (pf) {
            As[nxt][aCol + 0][aRow] = a0.x; As[nxt][aCol + 1][aRow] = a0.y;
            As[nxt][aCol + 2][aRow] = a0.z; As[nxt][aCol + 3][aRow] = a0.w;
            As[nxt][aCol + 4][aRow] = a1.x; As[nxt][aCol + 5][aRow] = a1.y;
            As[nxt][aCol + 6][aRow] = a1.z; As[nxt][aCol + 7][aRow] = a1.w;
            cp_wait0();
        }
        __syncthreads();
    }

    // epilogue (identical numerics to R1..R10)
#pragma unroll
    for (int ip = 0; ip < 4; ip++) {
#pragma unroll
        for (int half = 0; half < 2; half++) {
            int i = ip * 2 + half;
            int row = by * TBM + ty * 8 + i;
            int col0 = bx * TBN + tx * 8;
            float* crow = Cm + (size_t)row * N + col0;
            const float* rrow = res ? res + (size_t)row * N + col0 : nullptr;
#pragma unroll
            for (int j = 0; j < 8; j++) {
                float lo, hi;
                unpack2(accp[ip][j], lo, hi);
                float v = half ? hi : lo;
                if (bias) v += bias[col0 + j];
                if (rrow) v += rrow[j];
                if (act) v = gelu_tanh(v);
                crow[j] = v;
            }
        }
    }
}

__global__ __launch_bounds__(256, 2) void sgemm_kernel(
    const float* __restrict__ A, const float* __restrict__ Bm,
    const float* __restrict__ bias, const float* __restrict__ res,
    const float* __restrict__ acnt,
    float* __restrict__ Cm, int M, int N, int K, int act) {
    gemm_body(A, Bm, bias, res, acnt, Cm, M, N, K, act, blockIdx.x, blockIdx.y);
}

// Batched QKV: grid.z selects {Wq->q, Wk->k, Wv->v}. One launch, tails pack.
__global__ __launch_bounds__(256, 2) void qkv_gemm_kernel(
    const float* __restrict__ A,
    const float* __restrict__ Bq, const float* __restrict__ Bk, const float* __restrict__ Bv,
    float* __restrict__ Cq, float* __restrict__ Ck, float* __restrict__ Cv,
    int M, int N, int K) {
    const float* Bm = (blockIdx.z == 0) ? Bq : (blockIdx.z == 1) ? Bk : Bv;
    float* Cm = (blockIdx.z == 0) ? Cq : (blockIdx.z == 1) ? Ck : Cv;
    gemm_body(A, Bm, nullptr, nullptr, nullptr, Cm, M, N, K, 0, blockIdx.x, blockIdx.y);
}

// ---------------- embedding ----------------
__global__ void embed_kernel(const float* __restrict__ past_x,
                             const float* __restrict__ past_y,
                             const float* __restrict__ future_x,
                             const float* __restrict__ W_emb,
                             const float* __restrict__ b_emb,
                             float* __restrict__ h) {
    int idx = blockIdx.x * blockDim.x + threadIdx.x;
    if (idx >= kB * kS * kD) return;
    int d = idx % kD;
    int s = (idx / kD) % kS;
    int b = idx / (kD * kS);
    float feat[kXD + 1];
    if (s < kSP) {
#pragma unroll
        for (int j = 0; j < kXD; j++) feat[j] = past_x[((size_t)b * kSP + s) * kXD + j];
        feat[kXD] = past_y[(size_t)b * kSP + s];
    } else {
        int sf = s - kSP;
#pragma unroll
        for (int j = 0; j < kXD; j++) feat[j] = future_x[((size_t)b * kSF + sf) * kXD + j];
        feat[kXD] = past_y[(size_t)b * kSP + (kSP - 1)];
    }
    float acc = b_emb[d];
#pragma unroll
    for (int j = 0; j < kXD + 1; j++) acc += feat[j] * W_emb[(size_t)j * kD + d];
    h[idx] = acc;
}

// ---------------- layernorm (block per row, 128 threads) ----------------
// futureOnly: process only rows [b*kS+kSP, b*kS+kS) (the half consumed by heads)
__global__ void ln_kernel(const float* __restrict__ x, float* __restrict__ y,
                          const float* __restrict__ g, const float* __restrict__ bb,
                          int futureOnly) {
    __shared__ float red[8];
    int blk = blockIdx.x;
    int row = futureOnly ? (blk / kSF) * kS + kSP + (blk % kSF) : blk;
    int t = threadIdx.x;
    const float4 xv = ((const float4*)(x + (size_t)row * kD))[t];
    float s = xv.x + xv.y + xv.z + xv.w;
#pragma unroll
    for (int o = 16; o; o >>= 1) s += __shfl_xor_sync(0xffffffffu, s, o);
    if ((t & 31) == 0) red[t >> 5] = s;
    __syncthreads();
    float mean = (red[0] + red[1] + red[2] + red[3]) * (1.0f / kD);
    float dx = xv.x - mean, dy = xv.y - mean, dz = xv.z - mean, dw = xv.w - mean;
    float s2 = dx * dx + dy * dy + dz * dz + dw * dw;
#pragma unroll
    for (int o = 16; o; o >>= 1) s2 += __shfl_xor_sync(0xffffffffu, s2, o);
    if ((t & 31) == 0) red[4 + (t >> 5)] = s2;
    __syncthreads();
    float var = (red[4] + red[5] + red[6] + red[7]) * (1.0f / kD);
    float rstd = rsqrtf(var + 1e-5f);
    const float4 gg = ((const float4*)g)[t];
    const float4 bv = ((const float4*)bb)[t];
    float4 o4;
    o4.x = dx * rstd * gg.x + bv.x;
    o4.y = dy * rstd * gg.y + bv.y;
    o4.z = dz * rstd * gg.z + bv.z;
    o4.w = dw * rstd * gg.w + bv.w;
    ((float4*)(y + (size_t)row * kD))[t] = o4;
}

// ---------------- routing scores (q and k in one launch) ----------------
__global__ void score2_kernel(const float* __restrict__ q,
                              const float* __restrict__ k,
                              const float* __restrict__ means,
                              float* __restrict__ scores) {
    int gb = blockIdx.x;
    int inst = gb / kM;
    int bs = gb % kM;
    const float* src = inst ? k : q;
    float* dst = scores + (size_t)inst * kNBHC * kS;
    int b = bs / kS, s = bs % kS;
    int h = threadIdx.x >> 5, lane = threadIdx.x & 31;
    const float* qrow = src + (size_t)bs * kD + h * kDH;
    float qa = qrow[lane], qb = qrow[lane + 32];
    float nrm = qa * qa + qb * qb;
#pragma unroll
    for (int o = 16; o; o >>= 1) nrm += __shfl_xor_sync(0xffffffffu, nrm, o);
    float rn = rsqrtf(nrm + 1e-8f);
#pragma unroll
    for (int c = 0; c < kC; c++) {
        const float* mrow = means + ((size_t)h * kC + c) * kDH;
        float p = qa * mrow[lane] + qb * mrow[lane + 32];
#pragma unroll
        for (int o = 16; o; o >>= 1) p += __shfl_xor_sync(0xffffffffu, p, o);
        if (lane == 0)
            dst[(((size_t)b * kH + h) * kC + c) * kS + s] = p * rn;
    }
}

// ---------------- top-W via bitonic sort (q and k halves in one launch) ----------------
__global__ void topk_kernel(const float* __restrict__ scores, int* __restrict__ idxout) {
    __shared__ unsigned long long keys[kS];
    int blk = blockIdx.x;
    const float* sp = scores + (size_t)blk * kS;
    for (int i = threadIdx.x; i < kS; i += blockDim.x) {
        unsigned u = __float_as_uint(sp[i]);
        u = (u & 0x80000000u) ? ~u : (u | 0x80000000u);
        keys[i] = ((unsigned long long)u << 32) | (unsigned)i;
    }
    __syncthreads();
    for (int k = 2; k <= kS; k <<= 1) {
        for (int j = k >> 1; j > 0; j >>= 1) {
            for (int i = threadIdx.x; i < kS; i += blockDim.x) {
                int ixj = i ^ j;
                if (ixj > i) {
                    unsigned long long a = keys[i], b = keys[ixj];
                    bool up = ((i & k) == 0);
                    bool sw = up ? (a < b) : (a > b);
                    if (sw) { keys[i] = b; keys[ixj] = a; }
                }
            }
            __syncthreads();
        }
    }
    if (threadIdx.x < kW)
        idxout[(size_t)blk * kW + threadIdx.x] = (int)(keys[threadIdx.x] & 0xffffffffu);
}

// ---------------- within-cluster attention + scatter-add ----------------
__global__ __launch_bounds__(128) void attn_kernel(
    const float* __restrict__ q, const float* __restrict__ k, const float* __restrict__ v,
    const int* __restrict__ iq, const int* __restrict__ ik,
    float* __restrict__ attnout, float* __restrict__ cnt) {
    int blk = blockIdx.x;
    int h = (blk / kC) % kH;
    int b = blk / (kC * kH);
    extern __shared__ float smem[];
    float* ks = smem;
    float* vs = smem + kW * kDH;
    int t = threadIdx.x;
    const int* ikp = ik + (size_t)blk * kW;
    const int* iqp = iq + (size_t)blk * kW;
    {
        int sk = ikp[t];
        const float4* krow = (const float4*)(k + ((size_t)b * kS + sk) * kD + h * kDH);
        const float4* vrow = (const float4*)(v + ((size_t)b * kS + sk) * kD + h * kDH);
        float4* ksr = (float4*)(ks + (size_t)t * kDH);
        float4* vsr = (float4*)(vs + (size_t)t * kDH);
#pragma unroll
        for (int i = 0; i < kDH / 4; i++) { ksr[i] = krow[i]; vsr[i] = vrow[i]; }
    }
    __syncthreads();
    int sq = iqp[t];
    float qreg[kDH];
    {
        const float4* qrow = (const float4*)(q + ((size_t)b * kS + sq) * kD + h * kDH);
#pragma unroll
        for (int i = 0; i < kDH / 4; i++) ((float4*)qreg)[i] = qrow[i];
    }
    float m = -1e30f, l = 0.f;
    float accv[kDH];
#pragma unroll
    for (int d = 0; d < kDH; d++) accv[d] = 0.f;
    const float scale = 0.125f;

    for (int j = 0; j < kW; j++) {
        const float* kj = ks + (size_t)j * kDH;
        float s0 = 0, s1 = 0, s2 = 0, s3 = 0;
#pragma unroll
        for (int d = 0; d < kDH; d += 4) {
            s0 += qreg[d + 0] * kj[d + 0];
            s1 += qreg[d + 1] * kj[d + 1];
            s2 += qreg[d + 2] * kj[d + 2];
            s3 += qreg[d + 3] * kj[d + 3];
        }
        float s = (s0 + s1 + s2 + s3) * scale;
        float mn = fmaxf(m, s);
        float corr = __expf(m - mn);
        float p = __expf(s - mn);
        l = l * corr + p;
        const float* vj = vs + (size_t)j * kDH;
#pragma unroll
        for (int d = 0; d < kDH; d++) accv[d] = accv[d] * corr + p * vj[d];
        m = mn;
    }
    float inv = 1.0f / l;
    float* orow = attnout + ((size_t)b * kS + sq) * kD + h * kDH;
#pragma unroll
    for (int d = 0; d < kDH; d++) atomicAdd(orow + d, accv[d] * inv);
    atomicAdd(cnt + ((size_t)b * kH + h) * kS + sq, 1.0f);
}

// ---------------- output heads ----------------
__global__ void head_kernel(const float* __restrict__ hln,
                            const float* __restrict__ Wm, const float* __restrict__ bm,
                            const float* __restrict__ Ws, const float* __restrict__ bsd,
                            float* __restrict__ out) {
    int warp = (blockIdx.x * blockDim.x + threadIdx.x) >> 5;
    int lane = threadIdx.x & 31;
    if (warp >= kB * kSF) return;
    int b = warp / kSF, sf = warp % kSF;
    const float* row = hln + ((size_t)b * kS + kSP + sf) * kD;
    float mdot = 0.f, sdot = 0.f;
    for (int d = lane; d < kD; d += 32) {
        float x = row[d];
        mdot += x * Wm[d];
        sdot += x * Ws[d];
    }
#pragma unroll
    for (int o = 16; o; o >>= 1) {
        mdot += __shfl_xor_sync(0xffffffffu, mdot, o);
        sdot += __shfl_xor_sync(0xffffffffu, sdot, o);
    }
    if (lane == 0) {
        out[warp] = mdot + bm[0];
        float ls = sdot + bsd[0];
        float sp = fmaxf(ls, 0.f) + log1pf(__expf(-fabsf(ls)));
        out[(size_t)kB * kSF + warp] = 0.01f + 0.99f * sp;
    }
}

// ---------------- host orchestration ----------------
static void launch_gemm(const float* A, const float* Bm, const float* bias,
                        const float* res, const float* acnt, float* C,
                        int M, int N, int K, int act) {
    dim3 grid(N / TBN, M / TBM);
    sgemm_kernel<<<grid, 256>>>(A, Bm, bias, res, acnt, C, M, N, K, act);
}

extern "C" void kernel_launch(void* const* d_in, const int* in_sizes, int n_in,
                              void* d_out, int out_size) {
    const float* past_x   = (const float*)d_in[0];
    const float* past_y   = (const float*)d_in[1];
    const float* future_x = (const float*)d_in[2];
    const float* W_emb    = (const float*)d_in[3];
    const float* b_emb    = (const float*)d_in[4];
    const float* ln1_g    = (const float*)d_in[5];
    const float* ln1_b    = (const float*)d_in[6];
    const float* Wq       = (const float*)d_in[7];
    const float* Wk       = (const float*)d_in[8];
    const float* Wv       = (const float*)d_in[9];
    const float* Wo       = (const float*)d_in[10];
    const float* means    = (const float*)d_in[11];
    const float* ln2_g    = (const float*)d_in[12];
    const float* ln2_b    = (const float*)d_in[13];
    const float* W1       = (const float*)d_in[14];
    const float* b1       = (const float*)d_in[15];
    const float* W2       = (const float*)d_in[16];
    const float* b2       = (const float*)d_in[17];
    const float* lnf_g    = (const float*)d_in[18];
    const float* lnf_b    = (const float*)d_in[19];
    const float* W_mean   = (const float*)d_in[20];
    const float* b_mean   = (const float*)d_in[21];
    const float* W_std    = (const float*)d_in[22];
    const float* b_std    = (const float*)d_in[23];

    void *ph, *pln, *pq, *pk, *pv, *pac, *pffn, *pscores, *pidx;
    cudaGetSymbolAddress(&ph, g_h);
    cudaGetSymbolAddress(&pln, g_ln);
    cudaGetSymbolAddress(&pq, g_q);
    cudaGetSymbolAddress(&pk, g_k);
    cudaGetSymbolAddress(&pv, g_v);
    cudaGetSymbolAddress(&pac, g_attncnt);
    cudaGetSymbolAddress(&pffn, g_ffn);
    cudaGetSymbolAddress(&pscores, g_scores);
    cudaGetSymbolAddress(&pidx, g_idx);
    float* h    = (float*)ph;
    float* ln   = (float*)pln;
    float* q    = (float*)pq;
    float* k    = (float*)pk;
    float* v    = (float*)pv;
    float* attn = (float*)pac;
    float* cnt  = (float*)pac + (size_t)kB * kS * kD;
    float* ffn  = (float*)pffn;
    float* scr  = (float*)pscores;
    int*   iq   = (int*)pidx;
    int*   ik   = (int*)pidx + (size_t)kNBHC * kW;

    const int attn_smem = 2 * kW * kDH * (int)sizeof(float);  // 64 KB
    cudaFuncSetAttribute(attn_kernel, cudaFuncAttributeMaxDynamicSharedMemorySize, attn_smem);

    {
        int total = kB * kS * kD;
        embed_kernel<<<(total + 255) / 256, 256>>>(past_x, past_y, future_x, W_emb, b_emb, h);
    }

    const size_t attncnt_bytes = ((size_t)kB * kS * kD + (size_t)kB * kH * kS) * sizeof(float);

    for (int l = 0; l < kL; l++) {
        const float* mns = means + (size_t)l * kH * kC * kDH;
        // --- attention block ---
        ln_kernel<<<kM, 128>>>(h, ln, ln1_g + (size_t)l * kD, ln1_b + (size_t)l * kD, 0);
        // Q, K, V in a single launch: grid.z=3, tails pack together
        {
            dim3 grid(kD / TBN, kM / TBM, 3);
            qkv_gemm_kernel<<<grid, 256>>>(
                ln, Wq + (size_t)l * kD * kD, Wk + (size_t)l * kD * kD, Wv + (size_t)l * kD * kD,
                q, k, v, kM, kD, kD);
        }

        score2_kernel<<<2 * kM, 256>>>(q, k, mns, scr);
        topk_kernel<<<2 * kNBHC, 1024>>>(scr, (int*)pidx);

        cudaMemsetAsync(attn, 0, attncnt_bytes, 0);
        attn_kernel<<<kNBHC, 128, attn_smem>>>(q, k, v, iq, ik, attn, cnt);

        // h = h + (attn/cnt) @ Wo
        launch_gemm(attn, Wo + (size_t)l * kD * kD, nullptr, h, cnt, h, kM, kD, kD, 0);

        // --- FFN block ---
        ln_kernel<<<kM, 128>>>(h, ln, ln2_g + (size_t)l * kD, ln2_b + (size_t)l * kD, 0);
        launch_gemm(ln, W1 + (size_t)l * kD * kFF, b1 + (size_t)l * kFF, nullptr, nullptr, ffn, kM, kFF, kD, 1);
        launch_gemm(ffn, W2 + (size_t)l * kFF * kD, b2 + (size_t)l * kD, h, nullptr, h, kM, kD, kFF, 0);
    }

    // final LN + heads: only the future half is consumed
    ln_kernel<<<kB * kSF, 128>>>(h, ln, lnf_g, lnf_b, 1);
    {
        int warps = kB * kSF;
        int threads = warps * 32;
        head_kernel<<<(threads + 255) / 256, 256>>>(ln, W_mean, b_mean, W_std, b_std, (float*)d_out);
    }
}

// round 12
// speedup vs baseline: 1.1670x; 1.0302x over previous
#include <cuda_runtime.h>
#include <cstdint>
#include <cstddef>

// ---------------- problem dims ----------------
#define kB   8
#define kSP  1024
#define kSF  1024
#define kS   2048
#define kXD  6
#define kD   512
#define kL   4
#define kH   8
#define kW   128
#define kDH  64
#define kC   16
#define kFF  2048
#define kM   (kB * kS)          // 16384 rows
#define kNBHC (kB * kH * kC)    // 1024

typedef unsigned long long u64;

// ---------------- scratch (__device__ globals; no runtime alloc) ----------------
__device__ float g_h   [(size_t)kB * kS * kD];
__device__ float g_ln  [(size_t)kB * kS * kD];
__device__ float g_q   [(size_t)kB * kS * kD];
__device__ float g_k   [(size_t)kB * kS * kD];
__device__ float g_v   [(size_t)kB * kS * kD];
// attn accumulator + cnt merged: one memset covers both
__device__ float g_attncnt[(size_t)kB * kS * kD + (size_t)kB * kH * kS];
__device__ float g_ffn [(size_t)kB * kS * kFF];
__device__ float g_scores[(size_t)2 * kNBHC * kS];     // [0]=q scores, [1]=k scores
__device__ int   g_idx [(size_t)2 * kNBHC * kW];       // [0]=iq, [1]=ik

// ---------------- helpers ----------------
__device__ __forceinline__ float gelu_tanh(float x) {
    float x3 = x * x * x;
    return 0.5f * x * (1.0f + tanhf(0.7978845608028654f * (x + 0.044715f * x3)));
}

__device__ __forceinline__ uint32_t smem_u32(const void* p) {
    uint32_t a;
    asm("{ .reg .u64 t; cvta.to.shared.u64 t, %1; cvt.u32.u64 %0, t; }" : "=r"(a) : "l"(p));
    return a;
}

__device__ __forceinline__ void cp_async16(uint32_t dst, const void* src) {
    asm volatile("cp.async.cg.shared.global [%0], [%1], 16;" :: "r"(dst), "l"(src) : "memory");
}
__device__ __forceinline__ void cp_commit() { asm volatile("cp.async.commit_group;" ::: "memory"); }
__device__ __forceinline__ void cp_wait0()  { asm volatile("cp.async.wait_group 0;" ::: "memory"); }

// packed fp32x2 helpers (each lane is exact IEEE fp32 fma.rn)
__device__ __forceinline__ u64 splat2(float x) {
    u64 r; asm("mov.b64 %0, {%1, %1};" : "=l"(r) : "f"(x)); return r;
}
__device__ __forceinline__ void ffma2(u64& c, u64 a, u64 b) {
    asm("fma.rn.f32x2 %0, %1, %2, %0;" : "+l"(c) : "l"(a), "l"(b));
}
__device__ __forceinline__ void unpack2(u64 v, float& lo, float& hi) {
    asm("mov.b64 {%0, %1}, %2;" : "=f"(lo), "=f"(hi) : "l"(v));
}

// ---------------- fp32 GEMM tile body (TBK=16, cp.async double-buffered) ----------------
// Per-output FMA order identical to the R1 kernel (serial k ascending).
#define TBM 128
#define TBN 128
#define TBK 16
__device__ __forceinline__ void gemm_body(
    const float* __restrict__ A, const float* __restrict__ Bm,
    const float* __restrict__ bias, const float* __restrict__ res,
    const float* __restrict__ acnt,
    float* __restrict__ Cm, int M, int N, int K, int act, int bx, int by) {
    __shared__ float As[2][TBK][TBM];
    __shared__ float Bs[2][TBK][TBN];
    int tid = threadIdx.x;
    int tx = tid % 16, ty = tid / 16;
    const float* Ab = A + (size_t)by * TBM * K;
    const float* Bb = Bm + (size_t)bx * TBN;

    u64 accp[4][8];
#pragma unroll
    for (int ip = 0; ip < 4; ip++)
#pragma unroll
        for (int j = 0; j < 8; j++) accp[ip][j] = 0ull;

    int aRow = tid >> 1, aCol = (tid & 1) * 8;
    int bRow = tid >> 5, bCol = (tid & 31) * 4;

    uint32_t bs_base = smem_u32(&Bs[0][0][0]);
    const float* Aptr = Ab + (size_t)aRow * K + aCol;

    int grow = by * TBM + aRow;
    int cb = grow / kS, cs = grow % kS;
    const float* cnt_row = acnt ? acnt + ((size_t)cb * kH) * kS + cs : nullptr;

    // prologue: fill buffer 0 with k-block 0
    {
        cp_async16(bs_base + ((size_t)(0 * TBK + bRow) * TBN + bCol) * 4,
                   Bb + (size_t)bRow * N + bCol);
        cp_async16(bs_base + ((size_t)(0 * TBK + bRow + 8) * TBN + bCol) * 4,
                   Bb + (size_t)(bRow + 8) * N + bCol);
        cp_commit();
        float4 a0 = *(const float4*)(Aptr);
        float4 a1 = *(const float4*)(Aptr + 4);
        if (cnt_row) {
            int hh = aCol >> 6;
            float c = fmaxf(cnt_row[(size_t)hh * kS], 1.0f);
            a0.x /= c; a0.y /= c; a0.z /= c; a0.w /= c;
            a1.x /= c; a1.y /= c; a1.z /= c; a1.w /= c;
        }
        As[0][aCol + 0][aRow] = a0.x; As[0][aCol + 1][aRow] = a0.y;
        As[0][aCol + 2][aRow] = a0.z; As[0][aCol + 3][aRow] = a0.w;
        As[0][aCol + 4][aRow] = a1.x; As[0][aCol + 5][aRow] = a1.y;
        As[0][aCol + 6][aRow] = a1.z; As[0][aCol + 7][aRow] = a1.w;
        cp_wait0();
    }
    __syncthreads();

    int nk = K / TBK;
    for (int kb = 0; kb < nk; kb++) {
        int cur = kb & 1, nxt = cur ^ 1;
        float4 a0, a1;
        bool pf = (kb + 1 < nk);
        if (pf) {
            int k0 = (kb + 1) * TBK;
            cp_async16(bs_base + ((size_t)(nxt * TBK + bRow) * TBN + bCol) * 4,
                       Bb + (size_t)(k0 + bRow) * N + bCol);
            cp_async16(bs_base + ((size_t)(nxt * TBK + bRow + 8) * TBN + bCol) * 4,
                       Bb + (size_t)(k0 + bRow + 8) * N + bCol);
            cp_commit();
            a0 = *(const float4*)(Aptr + k0);
            a1 = *(const float4*)(Aptr + k0 + 4);
            if (cnt_row) {
                int hh = (k0 + aCol) >> 6;
                float c = fmaxf(cnt_row[(size_t)hh * kS], 1.0f);
                a0.x /= c; a0.y /= c; a0.z /= c; a0.w /= c;
                a1.x /= c; a1.y /= c; a1.z /= c; a1.w /= c;
            }
        }
#pragma unroll
        for (int k = 0; k < TBK; k++) {
            u64 ap[4];
            *(float4*)(&ap[0]) = *(const float4*)(&As[cur][k][ty * 8 + 0]);
            *(float4*)(&ap[2]) = *(const float4*)(&As[cur][k][ty * 8 + 4]);
            float br[8];
            *(float4*)(br + 0) = *(const float4*)(&Bs[cur][k][tx * 8 + 0]);
            *(float4*)(br + 4) = *(const float4*)(&Bs[cur][k][tx * 8 + 4]);
            u64 bd[8];
#pragma unroll
            for (int j = 0; j < 8; j++) bd[j] = splat2(br[j]);
#pragma unroll
            for (int ip = 0; ip < 4; ip++)
#pragma unroll
                for (int j = 0; j < 8; j++) ffma2(accp[ip][j], ap[ip], bd[j]);
        }
        if (pf) {
            As[nxt][aCol + 0][aRow] = a0.x; As[nxt][aCol + 1][aRow] = a0.y;
            As[nxt][aCol + 2][aRow] = a0.z; As[nxt][aCol + 3][aRow] = a0.w;
            As[nxt][aCol + 4][aRow] = a1.x; As[nxt][aCol + 5][aRow] = a1.y;
            As[nxt][aCol + 6][aRow] = a1.z; As[nxt][aCol + 7][aRow] = a1.w;
            cp_wait0();
        }
        __syncthreads();
    }

    // epilogue (identical numerics to R1..R11)
#pragma unroll
    for (int ip = 0; ip < 4; ip++) {
#pragma unroll
        for (int half = 0; half < 2; half++) {
            int i = ip * 2 + half;
            int row = by * TBM + ty * 8 + i;
            int col0 = bx * TBN + tx * 8;
            float* crow = Cm + (size_t)row * N + col0;
            const float* rrow = res ? res + (size_t)row * N + col0 : nullptr;
#pragma unroll
            for (int j = 0; j < 8; j++) {
                float lo, hi;
                unpack2(accp[ip][j], lo, hi);
                float v = half ? hi : lo;
                if (bias) v += bias[col0 + j];
                if (rrow) v += rrow[j];
                if (act) v = gelu_tanh(v);
                crow[j] = v;
            }
        }
    }
}

__global__ __launch_bounds__(256, 2) void sgemm_kernel(
    const float* __restrict__ A, const float* __restrict__ Bm,
    const float* __restrict__ bias, const float* __restrict__ res,
    const float* __restrict__ acnt,
    float* __restrict__ Cm, int M, int N, int K, int act) {
    gemm_body(A, Bm, bias, res, acnt, Cm, M, N, K, act, blockIdx.x, blockIdx.y);
}

// Batched QKV: grid.z selects {Wq->q, Wk->k, Wv->v}. One launch, tails pack.
__global__ __launch_bounds__(256, 2) void qkv_gemm_kernel(
    const float* __restrict__ A,
    const float* __restrict__ Bq, const float* __restrict__ Bk, const float* __restrict__ Bv,
    float* __restrict__ Cq, float* __restrict__ Ck, float* __restrict__ Cv,
    int M, int N, int K) {
    const float* Bm = (blockIdx.z == 0) ? Bq : (blockIdx.z == 1) ? Bk : Bv;
    float* Cm = (blockIdx.z == 0) ? Cq : (blockIdx.z == 1) ? Ck : Cv;
    gemm_body(A, Bm, nullptr, nullptr, nullptr, Cm, M, N, K, 0, blockIdx.x, blockIdx.y);
}

// ---------------- embedding ----------------
__global__ void embed_kernel(const float* __restrict__ past_x,
                             const float* __restrict__ past_y,
                             const float* __restrict__ future_x,
                             const float* __restrict__ W_emb,
                             const float* __restrict__ b_emb,
                             float* __restrict__ h) {
    int idx = blockIdx.x * blockDim.x + threadIdx.x;
    if (idx >= kB * kS * kD) return;
    int d = idx % kD;
    int s = (idx / kD) % kS;
    int b = idx / (kD * kS);
    float feat[kXD + 1];
    if (s < kSP) {
#pragma unroll
        for (int j = 0; j < kXD; j++) feat[j] = past_x[((size_t)b * kSP + s) * kXD + j];
        feat[kXD] = past_y[(size_t)b * kSP + s];
    } else {
        int sf = s - kSP;
#pragma unroll
        for (int j = 0; j < kXD; j++) feat[j] = future_x[((size_t)b * kSF + sf) * kXD + j];
        feat[kXD] = past_y[(size_t)b * kSP + (kSP - 1)];
    }
    float acc = b_emb[d];
#pragma unroll
    for (int j = 0; j < kXD + 1; j++) acc += feat[j] * W_emb[(size_t)j * kD + d];
    h[idx] = acc;
}

// ---------------- layernorm (block per row, 128 threads) ----------------
__global__ void ln_kernel(const float* __restrict__ x, float* __restrict__ y,
                          const float* __restrict__ g, const float* __restrict__ bb,
                          int futureOnly) {
    __shared__ float red[8];
    int blk = blockIdx.x;
    int row = futureOnly ? (blk / kSF) * kS + kSP + (blk % kSF) : blk;
    int t = threadIdx.x;
    const float4 xv = ((const float4*)(x + (size_t)row * kD))[t];
    float s = xv.x + xv.y + xv.z + xv.w;
#pragma unroll
    for (int o = 16; o; o >>= 1) s += __shfl_xor_sync(0xffffffffu, s, o);
    if ((t & 31) == 0) red[t >> 5] = s;
    __syncthreads();
    float mean = (red[0] + red[1] + red[2] + red[3]) * (1.0f / kD);
    float dx = xv.x - mean, dy = xv.y - mean, dz = xv.z - mean, dw = xv.w - mean;
    float s2 = dx * dx + dy * dy + dz * dz + dw * dw;
#pragma unroll
    for (int o = 16; o; o >>= 1) s2 += __shfl_xor_sync(0xffffffffu, s2, o);
    if ((t & 31) == 0) red[4 + (t >> 5)] = s2;
    __syncthreads();
    float var = (red[4] + red[5] + red[6] + red[7]) * (1.0f / kD);
    float rstd = rsqrtf(var + 1e-5f);
    const float4 gg = ((const float4*)g)[t];
    const float4 bv = ((const float4*)bb)[t];
    float4 o4;
    o4.x = dx * rstd * gg.x + bv.x;
    o4.y = dy * rstd * gg.y + bv.y;
    o4.z = dz * rstd * gg.z + bv.z;
    o4.w = dw * rstd * gg.w + bv.w;
    ((float4*)(y + (size_t)row * kD))[t] = o4;
}

// ---------------- routing scores: shuffle-free, bit-identical reduction tree ----------------
// One thread per (b,h,s). The serial tree  for o=16..1: p[l]+=p[l+o]  reproduces
// lane 0 of the old shfl_xor reduction exactly over identical per-lane partials.
__global__ __launch_bounds__(128) void score2_kernel(
    const float* __restrict__ q, const float* __restrict__ k,
    const float* __restrict__ means, float* __restrict__ scores) {
    // grid.x = 2 * kB * kH * (kS/128) = 2048; per-instance = 1024 blocks
    int blk = blockIdx.x;
    int inst = blk >> 10;
    int rem = blk & 1023;
    int b = rem >> 7;          // 8 h * 16 s-tiles = 128 per b
    int h = (rem >> 4) & 7;
    int st = rem & 15;
    const float* src = inst ? k : q;
    float* dst = scores + (size_t)inst * kNBHC * kS;
    int t = threadIdx.x;
    int s = st * 128 + t;

    __shared__ float ms[kC * kDH];
    for (int i = t; i < kC * kDH; i += 128)
        ms[i] = means[(size_t)h * kC * kDH + i];
    __syncthreads();

    float qv[kDH];
    const float4* qrow = (const float4*)(src + ((size_t)b * kS + s) * kD + h * kDH);
#pragma unroll
    for (int i = 0; i < kDH / 4; i++) ((float4*)qv)[i] = qrow[i];

    // norm (same per-lane partials + same tree as the old shfl_xor version)
    float p[32];
#pragma unroll
    for (int l = 0; l < 32; l++) p[l] = qv[l] * qv[l] + qv[l + 32] * qv[l + 32];
#pragma unroll
    for (int o = 16; o; o >>= 1)
#pragma unroll
        for (int l = 0; l < o; l++) p[l] += p[l + o];
    float rn = rsqrtf(p[0] + 1e-8f);

    float* out = dst + (((size_t)b * kH + h) * kC) * kS + s;
#pragma unroll
    for (int c = 0; c < kC; c++) {
        const float* mrow = ms + c * kDH;
        float pp[32];
#pragma unroll
        for (int l = 0; l < 32; l++) pp[l] = qv[l] * mrow[l] + qv[l + 32] * mrow[l + 32];
#pragma unroll
        for (int o = 16; o; o >>= 1)
#pragma unroll
            for (int l = 0; l < o; l++) pp[l] += pp[l + o];
        out[(size_t)c * kS] = pp[0] * rn;
    }
}

// ---------------- top-W via bitonic sort (q and k halves in one launch) ----------------
__global__ void topk_kernel(const float* __restrict__ scores, int* __restrict__ idxout) {
    __shared__ unsigned long long keys[kS];
    int blk = blockIdx.x;
    const float* sp = scores + (size_t)blk * kS;
    for (int i = threadIdx.x; i < kS; i += blockDim.x) {
        unsigned u = __float_as_uint(sp[i]);
        u = (u & 0x80000000u) ? ~u : (u | 0x80000000u);
        keys[i] = ((unsigned long long)u << 32) | (unsigned)i;
    }
    __syncthreads();
    for (int k = 2; k <= kS; k <<= 1) {
        for (int j = k >> 1; j > 0; j >>= 1) {
            for (int i = threadIdx.x; i < kS; i += blockDim.x) {
                int ixj = i ^ j;
                if (ixj > i) {
                    unsigned long long a = keys[i], b = keys[ixj];
                    bool up = ((i & k) == 0);
                    bool sw = up ? (a < b) : (a > b);
                    if (sw) { keys[i] = b; keys[ixj] = a; }
                }
            }
            __syncthreads();
        }
    }
    if (threadIdx.x < kW)
        idxout[(size_t)blk * kW + threadIdx.x] = (int)(keys[threadIdx.x] & 0xffffffffu);
}

// ---------------- within-cluster attention + scatter-add ----------------
__global__ __launch_bounds__(128) void attn_kernel(
    const float* __restrict__ q, const float* __restrict__ k, const float* __restrict__ v,
    const int* __restrict__ iq, const int* __restrict__ ik,
    float* __restrict__ attnout, float* __restrict__ cnt) {
    int blk = blockIdx.x;
    int h = (blk / kC) % kH;
    int b = blk / (kC * kH);
    extern __shared__ float smem[];
    float* ks = smem;
    float* vs = smem + kW * kDH;
    int t = threadIdx.x;
    const int* ikp = ik + (size_t)blk * kW;
    const int* iqp = iq + (size_t)blk * kW;
    {
        int sk = ikp[t];
        const float4* krow = (const float4*)(k + ((size_t)b * kS + sk) * kD + h * kDH);
        const float4* vrow = (const float4*)(v + ((size_t)b * kS + sk) * kD + h * kDH);
        float4* ksr = (float4*)(ks + (size_t)t * kDH);
        float4* vsr = (float4*)(vs + (size_t)t * kDH);
#pragma unroll
        for (int i = 0; i < kDH / 4; i++) { ksr[i] = krow[i]; vsr[i] = vrow[i]; }
    }
    __syncthreads();
    int sq = iqp[t];
    float qreg[kDH];
    {
        const float4* qrow = (const float4*)(q + ((size_t)b * kS + sq) * kD + h * kDH);
#pragma unroll
        for (int i = 0; i < kDH / 4; i++) ((float4*)qreg)[i] = qrow[i];
    }
    float m = -1e30f, l = 0.f;
    float accv[kDH];
#pragma unroll
    for (int d = 0; d < kDH; d++) accv[d] = 0.f;
    const float scale = 0.125f;

    for (int j = 0; j < kW; j++) {
        const float* kj = ks + (size_t)j * kDH;
        float s0 = 0, s1 = 0, s2 = 0, s3 = 0;
#pragma unroll
        for (int d = 0; d < kDH; d += 4) {
            s0 += qreg[d + 0] * kj[d + 0];
            s1 += qreg[d + 1] * kj[d + 1];
            s2 += qreg[d + 2] * kj[d + 2];
            s3 += qreg[d + 3] * kj[d + 3];
        }
        float s = (s0 + s1 + s2 + s3) * scale;
        float mn = fmaxf(m, s);
        float corr = __expf(m - mn);
        float p = __expf(s - mn);
        l = l * corr + p;
        const float* vj = vs + (size_t)j * kDH;
#pragma unroll
        for (int d = 0; d < kDH; d++) accv[d] = accv[d] * corr + p * vj[d];
        m = mn;
    }
    float inv = 1.0f / l;
    float* orow = attnout + ((size_t)b * kS + sq) * kD + h * kDH;
#pragma unroll
    for (int d = 0; d < kDH; d++) atomicAdd(orow + d, accv[d] * inv);
    atomicAdd(cnt + ((size_t)b * kH + h) * kS + sq, 1.0f);
}

// ---------------- output heads ----------------
__global__ void head_kernel(const float* __restrict__ hln,
                            const float* __restrict__ Wm, const float* __restrict__ bm,
                            const float* __restrict__ Ws, const float* __restrict__ bsd,
                            float* __restrict__ out) {
    int warp = (blockIdx.x * blockDim.x + threadIdx.x) >> 5;
    int lane = threadIdx.x & 31;
    if (warp >= kB * kSF) return;
    int b = warp / kSF, sf = warp % kSF;
    const float* row = hln + ((size_t)b * kS + kSP + sf) * kD;
    float mdot = 0.f, sdot = 0.f;
    for (int d = lane; d < kD; d += 32) {
        float x = row[d];
        mdot += x * Wm[d];
        sdot += x * Ws[d];
    }
#pragma unroll
    for (int o = 16; o; o >>= 1) {
        mdot += __shfl_xor_sync(0xffffffffu, mdot, o);
        sdot += __shfl_xor_sync(0xffffffffu, sdot, o);
    }
    if (lane == 0) {
        out[warp] = mdot + bm[0];
        float ls = sdot + bsd[0];
        float sp = fmaxf(ls, 0.f) + log1pf(__expf(-fabsf(ls)));
        out[(size_t)kB * kSF + warp] = 0.01f + 0.99f * sp;
    }
}

// ---------------- host orchestration ----------------
static void launch_gemm(const float* A, const float* Bm, const float* bias,
                        const float* res, const float* acnt, float* C,
                        int M, int N, int K, int act) {
    dim3 grid(N / TBN, M / TBM);
    sgemm_kernel<<<grid, 256>>>(A, Bm, bias, res, acnt, C, M, N, K, act);
}

extern "C" void kernel_launch(void* const* d_in, const int* in_sizes, int n_in,
                              void* d_out, int out_size) {
    const float* past_x   = (const float*)d_in[0];
    const float* past_y   = (const float*)d_in[1];
    const float* future_x = (const float*)d_in[2];
    const float* W_emb    = (const float*)d_in[3];
    const float* b_emb    = (const float*)d_in[4];
    const float* ln1_g    = (const float*)d_in[5];
    const float* ln1_b    = (const float*)d_in[6];
    const float* Wq       = (const float*)d_in[7];
    const float* Wk       = (const float*)d_in[8];
    const float* Wv       = (const float*)d_in[9];
    const float* Wo       = (const float*)d_in[10];
    const float* means    = (const float*)d_in[11];
    const float* ln2_g    = (const float*)d_in[12];
    const float* ln2_b    = (const float*)d_in[13];
    const float* W1       = (const float*)d_in[14];
    const float* b1       = (const float*)d_in[15];
    const float* W2       = (const float*)d_in[16];
    const float* b2       = (const float*)d_in[17];
    const float* lnf_g    = (const float*)d_in[18];
    const float* lnf_b    = (const float*)d_in[19];
    const float* W_mean   = (const float*)d_in[20];
    const float* b_mean   = (const float*)d_in[21];
    const float* W_std    = (const float*)d_in[22];
    const float* b_std    = (const float*)d_in[23];

    void *ph, *pln, *pq, *pk, *pv, *pac, *pffn, *pscores, *pidx;
    cudaGetSymbolAddress(&ph, g_h);
    cudaGetSymbolAddress(&pln, g_ln);
    cudaGetSymbolAddress(&pq, g_q);
    cudaGetSymbolAddress(&pk, g_k);
    cudaGetSymbolAddress(&pv, g_v);
    cudaGetSymbolAddress(&pac, g_attncnt);
    cudaGetSymbolAddress(&pffn, g_ffn);
    cudaGetSymbolAddress(&pscores, g_scores);
    cudaGetSymbolAddress(&pidx, g_idx);
    float* h    = (float*)ph;
    float* ln   = (float*)pln;
    float* q    = (float*)pq;
    float* k    = (float*)pk;
    float* v    = (float*)pv;
    float* attn = (float*)pac;
    float* cnt  = (float*)pac + (size_t)kB * kS * kD;
    float* ffn  = (float*)pffn;
    float* scr  = (float*)pscores;
    int*   iq   = (int*)pidx;
    int*   ik   = (int*)pidx + (size_t)kNBHC * kW;

    const int attn_smem = 2 * kW * kDH * (int)sizeof(float);  // 64 KB
    cudaFuncSetAttribute(attn_kernel, cudaFuncAttributeMaxDynamicSharedMemorySize, attn_smem);

    {
        int total = kB * kS * kD;
        embed_kernel<<<(total + 255) / 256, 256>>>(past_x, past_y, future_x, W_emb, b_emb, h);
    }

    const size_t attncnt_bytes = ((size_t)kB * kS * kD + (size_t)kB * kH * kS) * sizeof(float);

    for (int l = 0; l < kL; l++) {
        const float* mns = means + (size_t)l * kH * kC * kDH;
        // --- attention block ---
        ln_kernel<<<kM, 128>>>(h, ln, ln1_g + (size_t)l * kD, ln1_b + (size_t)l * kD, 0);
        {
            dim3 grid(kD / TBN, kM / TBM, 3);
            qkv_gemm_kernel<<<grid, 256>>>(
                ln, Wq + (size_t)l * kD * kD, Wk + (size_t)l * kD * kD, Wv + (size_t)l * kD * kD,
                q, k, v, kM, kD, kD);
        }

        score2_kernel<<<2 * kB * kH * (kS / 128), 128>>>(q, k, mns, scr);
        topk_kernel<<<2 * kNBHC, 1024>>>(scr, (int*)pidx);

        cudaMemsetAsync(attn, 0, attncnt_bytes, 0);
        attn_kernel<<<kNBHC, 128, attn_smem>>>(q, k, v, iq, ik, attn, cnt);

        // h = h + (attn/cnt) @ Wo
        launch_gemm(attn, Wo + (size_t)l * kD * kD, nullptr, h, cnt, h, kM, kD, kD, 0);

        // --- FFN block ---
        ln_kernel<<<kM, 128>>>(h, ln, ln2_g + (size_t)l * kD, ln2_b + (size_t)l * kD, 0);
        launch_gemm(ln, W1 + (size_t)l * kD * kFF, b1 + (size_t)l * kFF, nullptr, nullptr, ffn, kM, kFF, kD, 1);
        launch_gemm(ffn, W2 + (size_t)l * kFF * kD, b2 + (size_t)l * kD, h, nullptr, h, kM, kD, kFF, 0);
    }

    // final LN + heads: only the future half is consumed
    ln_kernel<<<kB * kSF, 128>>>(h, ln, lnf_g, lnf_b, 1);
    {
        int warps = kB * kSF;
        int threads = warps * 32;
        head_kernel<<<(threads + 255) / 256, 256>>>(ln, W_mean, b_mean, W_std, b_std, (float*)d_out);
    }
}

// round 13
// speedup vs baseline: 1.1820x; 1.0128x over previous
#include <cuda_runtime.h>
#include <cstdint>
#include <cstddef>

// ---------------- problem dims ----------------
#define kB   8
#define kSP  1024
#define kSF  1024
#define kS   2048
#define kXD  6
#define kD   512
#define kL   4
#define kH   8
#define kW   128
#define kDH  64
#define kC   16
#define kFF  2048
#define kM   (kB * kS)          // 16384 rows
#define kNBHC (kB * kH * kC)    // 1024

typedef unsigned long long u64;

// ---------------- scratch (__device__ globals; no runtime alloc) ----------------
__device__ float g_h   [(size_t)kB * kS * kD];
__device__ float g_ln  [(size_t)kB * kS * kD];
__device__ float g_q   [(size_t)kB * kS * kD];
__device__ float g_k   [(size_t)kB * kS * kD];
__device__ float g_v   [(size_t)kB * kS * kD];
__device__ float g_attncnt[(size_t)kB * kS * kD + (size_t)kB * kH * kS];
__device__ float g_ffn [(size_t)kB * kS * kFF];
__device__ float g_scores[(size_t)2 * kNBHC * kS];
__device__ int   g_idx [(size_t)2 * kNBHC * kW];

// ---------------- helpers ----------------
__device__ __forceinline__ float gelu_tanh(float x) {
    float x3 = x * x * x;
    return 0.5f * x * (1.0f + tanhf(0.7978845608028654f * (x + 0.044715f * x3)));
}

__device__ __forceinline__ uint32_t smem_u32(const void* p) {
    uint32_t a;
    asm("{ .reg .u64 t; cvta.to.shared.u64 t, %1; cvt.u32.u64 %0, t; }" : "=r"(a) : "l"(p));
    return a;
}

__device__ __forceinline__ void cp_async16(uint32_t dst, const void* src) {
    asm volatile("cp.async.cg.shared.global [%0], [%1], 16;" :: "r"(dst), "l"(src) : "memory");
}
__device__ __forceinline__ void cp_commit() { asm volatile("cp.async.commit_group;" ::: "memory"); }
__device__ __forceinline__ void cp_wait0()  { asm volatile("cp.async.wait_group 0;" ::: "memory"); }

__device__ __forceinline__ u64 splat2(float x) {
    u64 r; asm("mov.b64 %0, {%1, %1};" : "=l"(r) : "f"(x)); return r;
}
__device__ __forceinline__ void ffma2(u64& c, u64 a, u64 b) {
    asm("fma.rn.f32x2 %0, %1, %2, %0;" : "+l"(c) : "l"(a), "l"(b));
}
__device__ __forceinline__ void unpack2(u64 v, float& lo, float& hi) {
    asm("mov.b64 {%0, %1}, %2;" : "=f"(lo), "=f"(hi) : "l"(v));
}

// ---------------- fp32 GEMM tile body (TBK=16, cp.async double-buffered) ----------------
#define TBM 128
#define TBN 128
#define TBK 16
__device__ __forceinline__ void gemm_body(
    const float* __restrict__ A, const float* __restrict__ Bm,
    const float* __restrict__ bias, const float* __restrict__ res,
    const float* __restrict__ acnt,
    float* __restrict__ Cm, int M, int N, int K, int act, int bx, int by) {
    __shared__ float As[2][TBK][TBM];
    __shared__ float Bs[2][TBK][TBN];
    int tid = threadIdx.x;
    int tx = tid % 16, ty = tid / 16;
    const float* Ab = A + (size_t)by * TBM * K;
    const float* Bb = Bm + (size_t)bx * TBN;

    u64 accp[4][8];
#pragma unroll
    for (int ip = 0; ip < 4; ip++)
#pragma unroll
        for (int j = 0; j < 8; j++) accp[ip][j] = 0ull;

    int aRow = tid >> 1, aCol = (tid & 1) * 8;
    int bRow = tid >> 5, bCol = (tid & 31) * 4;

    uint32_t bs_base = smem_u32(&Bs[0][0][0]);
    const float* Aptr = Ab + (size_t)aRow * K + aCol;

    int grow = by * TBM + aRow;
    int cb = grow / kS, cs = grow % kS;
    const float* cnt_row = acnt ? acnt + ((size_t)cb * kH) * kS + cs : nullptr;

    {
        cp_async16(bs_base + ((size_t)(0 * TBK + bRow) * TBN + bCol) * 4,
                   Bb + (size_t)bRow * N + bCol);
        cp_async16(bs_base + ((size_t)(0 * TBK + bRow + 8) * TBN + bCol) * 4,
                   Bb + (size_t)(bRow + 8) * N + bCol);
        cp_commit();
        float4 a0 = *(const float4*)(Aptr);
        float4 a1 = *(const float4*)(Aptr + 4);
        if (cnt_row) {
            int hh = aCol >> 6;
            float c = fmaxf(cnt_row[(size_t)hh * kS], 1.0f);
            a0.x /= c; a0.y /= c; a0.z /= c; a0.w /= c;
            a1.x /= c; a1.y /= c; a1.z /= c; a1.w /= c;
        }
        As[0][aCol + 0][aRow] = a0.x; As[0][aCol + 1][aRow] = a0.y;
        As[0][aCol + 2][aRow] = a0.z; As[0][aCol + 3][aRow] = a0.w;
        As[0][aCol + 4][aRow] = a1.x; As[0][aCol + 5][aRow] = a1.y;
        As[0][aCol + 6][aRow] = a1.z; As[0][aCol + 7][aRow] = a1.w;
        cp_wait0();
    }
    __syncthreads();

    int nk = K / TBK;
    for (int kb = 0; kb < nk; kb++) {
        int cur = kb & 1, nxt = cur ^ 1;
        float4 a0, a1;
        bool pf = (kb + 1 < nk);
        if (pf) {
            int k0 = (kb + 1) * TBK;
            cp_async16(bs_base + ((size_t)(nxt * TBK + bRow) * TBN + bCol) * 4,
                       Bb + (size_t)(k0 + bRow) * N + bCol);
            cp_async16(bs_base + ((size_t)(nxt * TBK + bRow + 8) * TBN + bCol) * 4,
                       Bb + (size_t)(k0 + bRow + 8) * N + bCol);
            cp_commit();
            a0 = *(const float4*)(Aptr + k0);
            a1 = *(const float4*)(Aptr + k0 + 4);
            if (cnt_row) {
                int hh = (k0 + aCol) >> 6;
                float c = fmaxf(cnt_row[(size_t)hh * kS], 1.0f);
                a0.x /= c; a0.y /= c; a0.z /= c; a0.w /= c;
                a1.x /= c; a1.y /= c; a1.z /= c; a1.w /= c;
            }
        }
#pragma unroll
        for (int k = 0; k < TBK; k++) {
            u64 ap[4];
            *(float4*)(&ap[0]) = *(const float4*)(&As[cur][k][ty * 8 + 0]);
            *(float4*)(&ap[2]) = *(const float4*)(&As[cur][k][ty * 8 + 4]);
            float br[8];
            *(float4*)(br + 0) = *(const float4*)(&Bs[cur][k][tx * 8 + 0]);
            *(float4*)(br + 4) = *(const float4*)(&Bs[cur][k][tx * 8 + 4]);
            u64 bd[8];
#pragma unroll
            for (int j = 0; j < 8; j++) bd[j] = splat2(br[j]);
#pragma unroll
            for (int ip = 0; ip < 4; ip++)
#pragma unroll
                for (int j = 0; j < 8; j++) ffma2(accp[ip][j], ap[ip], bd[j]);
        }
        if (pf) {
            As[nxt][aCol + 0][aRow] = a0.x; As[nxt][aCol + 1][aRow] = a0.y;
            As[nxt][aCol + 2][aRow] = a0.z; As[nxt][aCol + 3][aRow] = a0.w;
            As[nxt][aCol + 4][aRow] = a1.x; As[nxt][aCol + 5][aRow] = a1.y;
            As[nxt][aCol + 6][aRow] = a1.z; As[nxt][aCol + 7][aRow] = a1.w;
            cp_wait0();
        }
        __syncthreads();
    }

#pragma unroll
    for (int ip = 0; ip < 4; ip++) {
#pragma unroll
        for (int half = 0; half < 2; half++) {
            int i = ip * 2 + half;
            int row = by * TBM + ty * 8 + i;
            int col0 = bx * TBN + tx * 8;
            float* crow = Cm + (size_t)row * N + col0;
            const float* rrow = res ? res + (size_t)row * N + col0 : nullptr;
#pragma unroll
            for (int j = 0; j < 8; j++) {
                float lo, hi;
                unpack2(accp[ip][j], lo, hi);
                float v = half ? hi : lo;
                if (bias) v += bias[col0 + j];
                if (rrow) v += rrow[j];
                if (act) v = gelu_tanh(v);
                crow[j] = v;
            }
        }
    }
}

__global__ __launch_bounds__(256, 2) void sgemm_kernel(
    const float* __restrict__ A, const float* __restrict__ Bm,
    const float* __restrict__ bias, const float* __restrict__ res,
    const float* __restrict__ acnt,
    float* __restrict__ Cm, int M, int N, int K, int act) {
    gemm_body(A, Bm, bias, res, acnt, Cm, M, N, K, act, blockIdx.x, blockIdx.y);
}

__global__ __launch_bounds__(256, 2) void qkv_gemm_kernel(
    const float* __restrict__ A,
    const float* __restrict__ Bq, const float* __restrict__ Bk, const float* __restrict__ Bv,
    float* __restrict__ Cq, float* __restrict__ Ck, float* __restrict__ Cv,
    int M, int N, int K) {
    const float* Bm = (blockIdx.z == 0) ? Bq : (blockIdx.z == 1) ? Bk : Bv;
    float* Cm = (blockIdx.z == 0) ? Cq : (blockIdx.z == 1) ? Ck : Cv;
    gemm_body(A, Bm, nullptr, nullptr, nullptr, Cm, M, N, K, 0, blockIdx.x, blockIdx.y);
}

// ---------------- embedding ----------------
__global__ void embed_kernel(const float* __restrict__ past_x,
                             const float* __restrict__ past_y,
                             const float* __restrict__ future_x,
                             const float* __restrict__ W_emb,
                             const float* __restrict__ b_emb,
                             float* __restrict__ h) {
    int idx = blockIdx.x * blockDim.x + threadIdx.x;
    if (idx >= kB * kS * kD) return;
    int d = idx % kD;
    int s = (idx / kD) % kS;
    int b = idx / (kD * kS);
    float feat[kXD + 1];
    if (s < kSP) {
#pragma unroll
        for (int j = 0; j < kXD; j++) feat[j] = past_x[((size_t)b * kSP + s) * kXD + j];
        feat[kXD] = past_y[(size_t)b * kSP + s];
    } else {
        int sf = s - kSP;
#pragma unroll
        for (int j = 0; j < kXD; j++) feat[j] = future_x[((size_t)b * kSF + sf) * kXD + j];
        feat[kXD] = past_y[(size_t)b * kSP + (kSP - 1)];
    }
    float acc = b_emb[d];
#pragma unroll
    for (int j = 0; j < kXD + 1; j++) acc += feat[j] * W_emb[(size_t)j * kD + d];
    h[idx] = acc;
}

// ---------------- layernorm (block per row, 128 threads) ----------------
__global__ void ln_kernel(const float* __restrict__ x, float* __restrict__ y,
                          const float* __restrict__ g, const float* __restrict__ bb,
                          int futureOnly) {
    __shared__ float red[8];
    int blk = blockIdx.x;
    int row = futureOnly ? (blk / kSF) * kS + kSP + (blk % kSF) : blk;
    int t = threadIdx.x;
    const float4 xv = ((const float4*)(x + (size_t)row * kD))[t];
    float s = xv.x + xv.y + xv.z + xv.w;
#pragma unroll
    for (int o = 16; o; o >>= 1) s += __shfl_xor_sync(0xffffffffu, s, o);
    if ((t & 31) == 0) red[t >> 5] = s;
    __syncthreads();
    float mean = (red[0] + red[1] + red[2] + red[3]) * (1.0f / kD);
    float dx = xv.x - mean, dy = xv.y - mean, dz = xv.z - mean, dw = xv.w - mean;
    float s2 = dx * dx + dy * dy + dz * dz + dw * dw;
#pragma unroll
    for (int o = 16; o; o >>= 1) s2 += __shfl_xor_sync(0xffffffffu, s2, o);
    if ((t & 31) == 0) red[4 + (t >> 5)] = s2;
    __syncthreads();
    float var = (red[4] + red[5] + red[6] + red[7]) * (1.0f / kD);
    float rstd = rsqrtf(var + 1e-5f);
    const float4 gg = ((const float4*)g)[t];
    const float4 bv = ((const float4*)bb)[t];
    float4 o4;
    o4.x = dx * rstd * gg.x + bv.x;
    o4.y = dy * rstd * gg.y + bv.y;
    o4.z = dz * rstd * gg.z + bv.z;
    o4.w = dw * rstd * gg.w + bv.w;
    ((float4*)(y + (size_t)row * kD))[t] = o4;
}

// ---------------- routing scores: shuffle-free, bit-identical reduction tree ----------------
__global__ __launch_bounds__(128) void score2_kernel(
    const float* __restrict__ q, const float* __restrict__ k,
    const float* __restrict__ means, float* __restrict__ scores) {
    int blk = blockIdx.x;
    int inst = blk >> 10;
    int rem = blk & 1023;
    int b = rem >> 7;
    int h = (rem >> 4) & 7;
    int st = rem & 15;
    const float* src = inst ? k : q;
    float* dst = scores + (size_t)inst * kNBHC * kS;
    int t = threadIdx.x;
    int s = st * 128 + t;

    __shared__ float ms[kC * kDH];
    for (int i = t; i < kC * kDH; i += 128)
        ms[i] = means[(size_t)h * kC * kDH + i];
    __syncthreads();

    float qv[kDH];
    const float4* qrow = (const float4*)(src + ((size_t)b * kS + s) * kD + h * kDH);
#pragma unroll
    for (int i = 0; i < kDH / 4; i++) ((float4*)qv)[i] = qrow[i];

    float p[32];
#pragma unroll
    for (int l = 0; l < 32; l++) p[l] = qv[l] * qv[l] + qv[l + 32] * qv[l + 32];
#pragma unroll
    for (int o = 16; o; o >>= 1)
#pragma unroll
        for (int l = 0; l < o; l++) p[l] += p[l + o];
    float rn = rsqrtf(p[0] + 1e-8f);

    float* out = dst + (((size_t)b * kH + h) * kC) * kS + s;
#pragma unroll
    for (int c = 0; c < kC; c++) {
        const float* mrow = ms + c * kDH;
        float pp[32];
#pragma unroll
        for (int l = 0; l < 32; l++) pp[l] = qv[l] * mrow[l] + qv[l + 32] * mrow[l + 32];
#pragma unroll
        for (int o = 16; o; o >>= 1)
#pragma unroll
            for (int l = 0; l < o; l++) pp[l] += pp[l + o];
        out[(size_t)c * kS] = pp[0] * rn;
    }
}

// ---------------- top-W: bitonic sort stages + prefix bitonic-splits ----------------
// Stages k=2..1024 fully sort halves; final k=2048 merge replaced by 4 splits
// (j=1024 full, then j=512/256/128 on shrinking prefixes) -> top-128 SET in keys[0..127].
// Set semantics suffice: downstream gather/softmax/scatter-mean are permutation-invariant.
__global__ __launch_bounds__(512) void topk_kernel(const float* __restrict__ scores,
                                                   int* __restrict__ idxout) {
    __shared__ unsigned long long keys[kS];
    int blk = blockIdx.x;
    const float* sp = scores + (size_t)blk * kS;
    for (int i = threadIdx.x; i < kS; i += 512) {
        unsigned u = __float_as_uint(sp[i]);
        u = (u & 0x80000000u) ? ~u : (u | 0x80000000u);
        keys[i] = ((unsigned long long)u << 32) | (unsigned)i;
    }
    __syncthreads();
    for (int k = 2; k <= 1024; k <<= 1) {
        for (int j = k >> 1; j > 0; j >>= 1) {
            for (int i = threadIdx.x; i < kS; i += 512) {
                int ixj = i ^ j;
                if (ixj > i) {
                    unsigned long long a = keys[i], b = keys[ixj];
                    bool up = ((i & k) == 0);
                    bool sw = up ? (a < b) : (a > b);
                    if (sw) { keys[i] = b; keys[ixj] = a; }
                }
            }
            __syncthreads();
        }
    }
    // final merge (direction: keep max at low index everywhere, as in the full sort)
#pragma unroll
    for (int half = 1024; half >= 128; half >>= 1) {
        for (int i = threadIdx.x; i < half; i += 512) {
            unsigned long long a = keys[i], b = keys[i + half];
            if (a < b) { keys[i] = b; keys[i + half] = a; }
        }
        __syncthreads();
    }
    if (threadIdx.x < kW)
        idxout[(size_t)blk * kW + threadIdx.x] = (int)(keys[threadIdx.x] & 0xffffffffu);
}

// ---------------- within-cluster attention + scatter-add ----------------
// Online softmax with branch: max-update path is arithmetically identical to the
// original (p=exp(0)=1 exactly); common path fuses p*v+acc into one fma (<=1ulp).
__global__ __launch_bounds__(128) void attn_kernel(
    const float* __restrict__ q, const float* __restrict__ k, const float* __restrict__ v,
    const int* __restrict__ iq, const int* __restrict__ ik,
    float* __restrict__ attnout, float* __restrict__ cnt) {
    int blk = blockIdx.x;
    int h = (blk / kC) % kH;
    int b = blk / (kC * kH);
    extern __shared__ float smem[];
    float* ks = smem;
    float* vs = smem + kW * kDH;
    int t = threadIdx.x;
    const int* ikp = ik + (size_t)blk * kW;
    const int* iqp = iq + (size_t)blk * kW;
    {
        int sk = ikp[t];
        const float4* krow = (const float4*)(k + ((size_t)b * kS + sk) * kD + h * kDH);
        const float4* vrow = (const float4*)(v + ((size_t)b * kS + sk) * kD + h * kDH);
        float4* ksr = (float4*)(ks + (size_t)t * kDH);
        float4* vsr = (float4*)(vs + (size_t)t * kDH);
#pragma unroll
        for (int i = 0; i < kDH / 4; i++) { ksr[i] = krow[i]; vsr[i] = vrow[i]; }
    }
    __syncthreads();
    int sq = iqp[t];
    float qreg[kDH];
    {
        const float4* qrow = (const float4*)(q + ((size_t)b * kS + sq) * kD + h * kDH);
#pragma unroll
        for (int i = 0; i < kDH / 4; i++) ((float4*)qreg)[i] = qrow[i];
    }
    float m = -1e30f, l = 0.f;
    float accv[kDH];
#pragma unroll
    for (int d = 0; d < kDH; d++) accv[d] = 0.f;
    const float scale = 0.125f;

    for (int j = 0; j < kW; j++) {
        const float* kj = ks + (size_t)j * kDH;
        float s0 = 0, s1 = 0, s2 = 0, s3 = 0;
#pragma unroll
        for (int d = 0; d < kDH; d += 4) {
            s0 += qreg[d + 0] * kj[d + 0];
            s1 += qreg[d + 1] * kj[d + 1];
            s2 += qreg[d + 2] * kj[d + 2];
            s3 += qreg[d + 3] * kj[d + 3];
        }
        float s = (s0 + s1 + s2 + s3) * scale;
        const float* vj = vs + (size_t)j * kDH;
        if (s > m) {
            // max update (rare): corr = exp(m-s); p = exp(0) = 1 exactly
            float corr = __expf(m - s);
            l = fmaf(l, corr, 1.0f);
#pragma unroll
            for (int d = 0; d < kDH; d++) accv[d] = fmaf(accv[d], corr, vj[d]);
            m = s;
        } else {
            // common: corr = exp(0) = 1 exactly; fused accumulate (<=1ulp vs mul+add)
            float p = __expf(s - m);
            l += p;
#pragma unroll
            for (int d = 0; d < kDH; d++) accv[d] = fmaf(p, vj[d], accv[d]);
        }
    }
    float inv = 1.0f / l;
    float* orow = attnout + ((size_t)b * kS + sq) * kD + h * kDH;
#pragma unroll
    for (int d = 0; d < kDH; d++) atomicAdd(orow + d, accv[d] * inv);
    atomicAdd(cnt + ((size_t)b * kH + h) * kS + sq, 1.0f);
}

// ---------------- output heads ----------------
__global__ void head_kernel(const float* __restrict__ hln,
                            const float* __restrict__ Wm, const float* __restrict__ bm,
                            const float* __restrict__ Ws, const float* __restrict__ bsd,
                            float* __restrict__ out) {
    int warp = (blockIdx.x * blockDim.x + threadIdx.x) >> 5;
    int lane = threadIdx.x & 31;
    if (warp >= kB * kSF) return;
    int b = warp / kSF, sf = warp % kSF;
    const float* row = hln + ((size_t)b * kS + kSP + sf) * kD;
    float mdot = 0.f, sdot = 0.f;
    for (int d = lane; d < kD; d += 32) {
        float x = row[d];
        mdot += x * Wm[d];
        sdot += x * Ws[d];
    }
#pragma unroll
    for (int o = 16; o; o >>= 1) {
        mdot += __shfl_xor_sync(0xffffffffu, mdot, o);
        sdot += __shfl_xor_sync(0xffffffffu, sdot, o);
    }
    if (lane == 0) {
        out[warp] = mdot + bm[0];
        float ls = sdot + bsd[0];
        float sp = fmaxf(ls, 0.f) + log1pf(__expf(-fabsf(ls)));
        out[(size_t)kB * kSF + warp] = 0.01f + 0.99f * sp;
    }
}

// ---------------- host orchestration ----------------
static void launch_gemm(const float* A, const float* Bm, const float* bias,
                        const float* res, const float* acnt, float* C,
                        int M, int N, int K, int act) {
    dim3 grid(N / TBN, M / TBM);
    sgemm_kernel<<<grid, 256>>>(A, Bm, bias, res, acnt, C, M, N, K, act);
}

extern "C" void kernel_launch(void* const* d_in, const int* in_sizes, int n_in,
                              void* d_out, int out_size) {
    const float* past_x   = (const float*)d_in[0];
    const float* past_y   = (const float*)d_in[1];
    const float* future_x = (const float*)d_in[2];
    const float* W_emb    = (const float*)d_in[3];
    const float* b_emb    = (const float*)d_in[4];
    const float* ln1_g    = (const float*)d_in[5];
    const float* ln1_b    = (const float*)d_in[6];
    const float* Wq       = (const float*)d_in[7];
    const float* Wk       = (const float*)d_in[8];
    const float* Wv       = (const float*)d_in[9];
    const float* Wo       = (const float*)d_in[10];
    const float* means    = (const float*)d_in[11];
    const float* ln2_g    = (const float*)d_in[12];
    const float* ln2_b    = (const float*)d_in[13];
    const float* W1       = (const float*)d_in[14];
    const float* b1       = (const float*)d_in[15];
    const float* W2       = (const float*)d_in[16];
    const float* b2       = (const float*)d_in[17];
    const float* lnf_g    = (const float*)d_in[18];
    const float* lnf_b    = (const float*)d_in[19];
    const float* W_mean   = (const float*)d_in[20];
    const float* b_mean   = (const float*)d_in[21];
    const float* W_std    = (const float*)d_in[22];
    const float* b_std    = (const float*)d_in[23];

    void *ph, *pln, *pq, *pk, *pv, *pac, *pffn, *pscores, *pidx;
    cudaGetSymbolAddress(&ph, g_h);
    cudaGetSymbolAddress(&pln, g_ln);
    cudaGetSymbolAddress(&pq, g_q);
    cudaGetSymbolAddress(&pk, g_k);
    cudaGetSymbolAddress(&pv, g_v);
    cudaGetSymbolAddress(&pac, g_attncnt);
    cudaGetSymbolAddress(&pffn, g_ffn);
    cudaGetSymbolAddress(&pscores, g_scores);
    cudaGetSymbolAddress(&pidx, g_idx);
    float* h    = (float*)ph;
    float* ln   = (float*)pln;
    float* q    = (float*)pq;
    float* k    = (float*)pk;
    float* v    = (float*)pv;
    float* attn = (float*)pac;
    float* cnt  = (float*)pac + (size_t)kB * kS * kD;
    float* ffn  = (float*)pffn;
    float* scr  = (float*)pscores;
    int*   iq   = (int*)pidx;
    int*   ik   = (int*)pidx + (size_t)kNBHC * kW;

    const int attn_smem = 2 * kW * kDH * (int)sizeof(float);  // 64 KB
    cudaFuncSetAttribute(attn_kernel, cudaFuncAttributeMaxDynamicSharedMemorySize, attn_smem);

    {
        int total = kB * kS * kD;
        embed_kernel<<<(total + 255) / 256, 256>>>(past_x, past_y, future_x, W_emb, b_emb, h);
    }

    const size_t attncnt_bytes = ((size_t)kB * kS * kD + (size_t)kB * kH * kS) * sizeof(float);

    for (int l = 0; l < kL; l++) {
        const float* mns = means + (size_t)l * kH * kC * kDH;
        // --- attention block ---
        ln_kernel<<<kM, 128>>>(h, ln, ln1_g + (size_t)l * kD, ln1_b + (size_t)l * kD, 0);
        {
            dim3 grid(kD / TBN, kM / TBM, 3);
            qkv_gemm_kernel<<<grid, 256>>>(
                ln, Wq + (size_t)l * kD * kD, Wk + (size_t)l * kD * kD, Wv + (size_t)l * kD * kD,
                q, k, v, kM, kD, kD);
        }

        score2_kernel<<<2 * kB * kH * (kS / 128), 128>>>(q, k, mns, scr);
        topk_kernel<<<2 * kNBHC, 512>>>(scr, (int*)pidx);

        cudaMemsetAsync(attn, 0, attncnt_bytes, 0);
        attn_kernel<<<kNBHC, 128, attn_smem>>>(q, k, v, iq, ik, attn, cnt);

        // h = h + (attn/cnt) @ Wo
        launch_gemm(attn, Wo + (size_t)l * kD * kD, nullptr, h, cnt, h, kM, kD, kD, 0);

        // --- FFN block ---
        ln_kernel<<<kM, 128>>>(h, ln, ln2_g + (size_t)l * kD, ln2_b + (size_t)l * kD, 0);
        launch_gemm(ln, W1 + (size_t)l * kD * kFF, b1 + (size_t)l * kFF, nullptr, nullptr, ffn, kM, kFF, kD, 1);
        launch_gemm(ffn, W2 + (size_t)l * kFF * kD, b2 + (size_t)l * kD, h, nullptr, h, kM, kD, kFF, 0);
    }

    // final LN + heads: only the future half is consumed
    ln_kernel<<<kB * kSF, 128>>>(h, ln, lnf_g, lnf_b, 1);
    {
        int warps = kB * kSF;
        int threads = warps * 32;
        head_kernel<<<(threads + 255) / 256, 256>>>(ln, W_mean, b_mean, W_std, b_std, (float*)d_out);
    }
}